// round 6
// baseline (speedup 1.0000x reference)
#include <cuda_runtime.h>
#include <cuda_bf16.h>
#include <stdint.h>

// ---------------- problem constants ----------------
#define BATCH   64
#define HDIM    512
#define WDIM    512
#define NPIX    (HDIM*WDIM)          // 262144
#define NWORDS  (NPIX/32)
#define NIMG    (2*BATCH)            // 128
#define NPTS    1000
#define NPTS4   1004
#define CANDCAP 4096
#define UTH     0.99277f             // E[accepted] ~ 0.00723*nvalid

// ---------------- device scratch ----------------
__device__ uint32_t g_keys[256];
__device__ uint32_t g_validbits[NIMG*NWORDS];
__device__ uint32_t g_nvalid[NIMG];
__device__ uint32_t g_candcnt[NIMG];
__device__ unsigned long long g_cand[(size_t)NIMG*CANDCAP];
__device__ float    g_lx[NIMG*NPTS4];
__device__ float    g_ly[NIMG*NPTS4];
__device__ float    g_q [NIMG*NPTS4];
__device__ int      g_np[NIMG];
__device__ float    g_hd[BATCH];
__device__ unsigned int g_done;

// ---------------- threefry2x32 (JAX partitionable semantics) ----------------
__device__ __forceinline__ uint32_t rotl32(uint32_t x, int r) {
    return __funnelshift_l(x, x, r);
}
__device__ __forceinline__ void threefry2x32(uint32_t k0, uint32_t k1,
                                             uint32_t x0, uint32_t x1,
                                             uint32_t& o0, uint32_t& o1) {
    uint32_t ks2 = k0 ^ k1 ^ 0x1BD11BDAu;
    x0 += k0; x1 += k1;
#define TF_RND(r) { x0 += x1; x1 = rotl32(x1, r); x1 ^= x0; }
    TF_RND(13) TF_RND(15) TF_RND(26) TF_RND(6)   x0 += k1;  x1 += ks2 + 1u;
    TF_RND(17) TF_RND(29) TF_RND(16) TF_RND(24)  x0 += ks2; x1 += k0  + 2u;
    TF_RND(13) TF_RND(15) TF_RND(26) TF_RND(6)   x0 += k0;  x1 += k1  + 3u;
    TF_RND(17) TF_RND(29) TF_RND(16) TF_RND(24)  x0 += k1;  x1 += ks2 + 4u;
    TF_RND(13) TF_RND(15) TF_RND(26) TF_RND(6)   x0 += ks2; x1 += k0  + 5u;
#undef TF_RND
    o0 = x0; o1 = x1;
}
__device__ __forceinline__ float bits_to_uniform(uint32_t bits) {
    return __uint_as_float((bits >> 9) | 0x3F800000u) - 1.0f;
}

// ---------------- kernels ----------------
// init: zero counters + compute partitionable split(key(1),128)
__global__ void k_init() {
    int i = threadIdx.x;
    if (i < NIMG) { g_candcnt[i] = 0u; g_nvalid[i] = 0u; }
    if (i == 0)   g_done = 0u;
    if (i < 128) {
        uint32_t o0, o1;
        threefry2x32(0u, 1u, 0u, (uint32_t)i, o0, o1);
        g_keys[2*i] = o0; g_keys[2*i + 1] = o1;
    }
}

// Fused: tiled Sobel (sigmoid fused for pred) + threefry + threshold accept.
__global__ void __launch_bounds__(256) k_fused(const float* __restrict__ pred,
                                               const float* __restrict__ target) {
    __shared__ float s[10][514];
    __shared__ unsigned int blkcnt;
    int bx  = blockIdx.x;
    int b   = bx >> 6;
    int r0  = (bx & 63) << 3;
    int tid = threadIdx.x;
    if (tid == 0) blkcnt = 0u;
    bool isPred = (b < BATCH);
    const float* src = isPred ? (pred + (size_t)b * NPIX)
                              : (target + (size_t)(b - BATCH) * NPIX);
    for (int idx = tid; idx < 1280; idx += 256) {
        int lr = idx >> 7;
        int c4 = (idx & 127) << 2;
        int gr = r0 + lr - 1;
        float4 v;
        if (gr >= 0 && gr < HDIM) {
            v = *reinterpret_cast<const float4*>(src + ((size_t)gr << 9) + c4);
            if (isPred) {
                v.x = 1.0f / (1.0f + expf(-v.x));
                v.y = 1.0f / (1.0f + expf(-v.y));
                v.z = 1.0f / (1.0f + expf(-v.z));
                v.w = 1.0f / (1.0f + expf(-v.w));
            }
        } else v = make_float4(0.f, 0.f, 0.f, 0.f);
        s[lr][1 + c4] = v.x; s[lr][2 + c4] = v.y;
        s[lr][3 + c4] = v.z; s[lr][4 + c4] = v.w;
        if (c4 == 0) { s[lr][0] = 0.f; s[lr][513] = 0.f; }
    }
    __syncthreads();
    uint32_t k0 = g_keys[2*b], k1 = g_keys[2*b + 1];
    int w = tid >> 5, lane = tid & 31;
    unsigned int myc = 0;
    for (int u = w; u < 128; u += 8) {
        int row8 = u >> 4, seg = u & 15;
        int sc = seg * 32 + lane + 1;
        float L0 = s[row8  ][sc-1], M0 = s[row8  ][sc], R0 = s[row8  ][sc+1];
        float L1 = s[row8+1][sc-1],                     R1 = s[row8+1][sc+1];
        float L2 = s[row8+2][sc-1], M2 = s[row8+2][sc], R2 = s[row8+2][sc+1];
        float gx = (R0 - L0) + 2.0f * (R1 - L1) + (R2 - L2);
        float gy = (L2 + 2.0f * M2 + R2) - (L0 + 2.0f * M0 + R0);
        float bm = sqrtf(gx * gx + gy * gy + 1e-8f);
        bool v = bm > 0.1f;
        int gr = r0 + row8;
        unsigned int word = __ballot_sync(0xffffffffu, v);
        if (lane == 0) {
            g_validbits[b * NWORDS + gr * 16 + seg] = word;
            myc += __popc(word);
        }
        int i = (gr << 9) + seg * 32 + lane;
        uint32_t o0, o1;
        threefry2x32(k0, k1, 0u, (uint32_t)i, o0, o1);
        float uu = bits_to_uniform(o0 ^ o1);
        bool acc = v && (uu > UTH);
        unsigned int amask = __ballot_sync(0xffffffffu, acc);
        if (amask) {
            int leader = __ffs(amask) - 1;
            uint32_t base = 0;
            if (lane == leader) base = atomicAdd(&g_candcnt[b], (uint32_t)__popc(amask));
            base = __shfl_sync(0xffffffffu, base, leader);
            if (acc) {
                uint32_t pos = base + __popc(amask & ((1u << lane) - 1u));
                if (pos < CANDCAP) {
                    uint32_t sb = __float_as_uint(2.0f + uu);
                    g_cand[(size_t)b * CANDCAP + pos] =
                        (((unsigned long long)sb) << 32) | (unsigned long long)(~(uint32_t)i);
                }
            }
        }
    }
    if (lane == 0 && myc) atomicAdd(&blkcnt, myc);
    __syncthreads();
    if (tid == 0 && blkcnt) atomicAdd(&g_nvalid[b], blkcnt);
}

// Sort + emit (rescue slow path inlined; never taken on sane inputs).
__global__ void __launch_bounds__(512) k_sort_emit() {
    __shared__ unsigned long long s[CANDCAP];
    __shared__ unsigned int rc;
    int b = blockIdx.x, tid = threadIdx.x, nt = blockDim.x;
    unsigned int cnt = g_candcnt[b]; if (cnt > CANDCAP) cnt = CANDCAP;
    unsigned int nv = g_nvalid[b];
    unsigned int needed = (nv < (unsigned)NPTS) ? nv : (unsigned)NPTS;
    if (cnt < needed) {
        // RESCUE: recompute with adaptive tau (guaranteed coverage)
        if (tid == 0) rc = 0u;
        __syncthreads();
        uint32_t k0 = g_keys[2*b], k1 = g_keys[2*b + 1];
        uint32_t tau = 0u;
        if (nv > 2500u)
            tau = __float_as_uint(2.0f + (1.0f - 2048.0f / (float)nv));
        int lane = tid & 31;
        for (int i = tid; i < NPIX; i += nt) {
            uint32_t vw = g_validbits[b * NWORDS + (i >> 5)];
            bool v = (vw >> lane) & 1u;
            uint32_t o0, o1;
            threefry2x32(k0, k1, 0u, (uint32_t)i, o0, o1);
            uint32_t sb = __float_as_uint(2.0f + bits_to_uniform(o0 ^ o1));
            bool acc = v && (sb >= tau);
            unsigned int amask = __ballot_sync(0xffffffffu, acc);
            if (amask) {
                int leader = __ffs(amask) - 1;
                uint32_t base = 0;
                if (lane == leader) base = atomicAdd(&rc, (uint32_t)__popc(amask));
                base = __shfl_sync(0xffffffffu, base, leader);
                if (acc) {
                    uint32_t pos = base + __popc(amask & ((1u << lane) - 1u));
                    if (pos < CANDCAP)
                        s[pos] = (((unsigned long long)sb) << 32)
                               | (unsigned long long)(~(uint32_t)i);
                }
            }
        }
        __syncthreads();
        cnt = rc; if (cnt > CANDCAP) cnt = CANDCAP;
    } else {
        for (unsigned int i = tid; i < cnt; i += nt)
            s[i] = g_cand[(size_t)b * CANDCAP + i];
    }
    int n = 2; while (n < (int)cnt) n <<= 1;
    for (int i = (int)cnt + tid; i < n; i += nt) s[i] = 0ull;   // pad
    __syncthreads();
    for (int k = 2; k <= n; k <<= 1) {
        for (int j = k >> 1; j > 0; j >>= 1) {
            for (int i = tid; i < n; i += nt) {
                int ixj = i ^ j;
                if (ixj > i) {
                    unsigned long long a = s[i], bb = s[ixj];
                    if ((a > bb) == ((i & k) == 0)) { s[i] = bb; s[ixj] = a; }
                }
            }
            __syncthreads();
        }
    }
    int need = (cnt < (unsigned)NPTS) ? (int)cnt : NPTS;
    int npts = (cnt == 0u) ? 1 : need;
    int pad  = (npts + 3) & ~3;
    for (int j = tid; j < pad; j += nt) {
        float x, y, q;
        if (j < npts) {
            if (cnt == 0u) { x = 256.0f; y = 256.0f; }
            else {
                unsigned long long key = s[n - 1 - j];
                uint32_t idx = ~(uint32_t)key;
                x = (float)(idx >> 9); y = (float)(idx & 511);
            }
            q = x * x + y * y;
        } else { x = 0.0f; y = 0.0f; q = 3.0e38f; }
        g_lx[b * NPTS4 + j] = x;
        g_ly[b * NPTS4 + j] = y;
        g_q [b * NPTS4 + j] = q;
    }
    if (tid == 0) g_np[b] = npts;
}

// Hausdorff in d^2 space with exact early termination; last block does mean.
__global__ void __launch_bounds__(512) k_hd_mean(float* __restrict__ out) {
    __shared__ __align__(16) float spx[NPTS4], spy[NPTS4], sqp[NPTS4];
    __shared__ __align__(16) float stx[NPTS4], sty[NPTS4], sqt[NPTS4];
    __shared__ unsigned int s_best;          // running max d^2 (float bits)
    __shared__ int s_last;
    int b = blockIdx.x;                      // 0..63
    int tid = threadIdx.x;
    int np = g_np[b], ntt = g_np[BATCH + b];
    int np4 = (np + 3) & ~3, nt4 = (ntt + 3) & ~3;
    if (tid == 0) { s_best = 0u; s_last = 0; }
    for (int i = tid; i < np4; i += 512) {
        spx[i] = g_lx[b * NPTS4 + i];
        spy[i] = g_ly[b * NPTS4 + i];
        sqp[i] = g_q [b * NPTS4 + i];
    }
    for (int i = tid; i < nt4; i += 512) {
        stx[i] = g_lx[(BATCH + b) * NPTS4 + i];
        sty[i] = g_ly[(BATCH + b) * NPTS4 + i];
        sqt[i] = g_q [(BATCH + b) * NPTS4 + i];
    }
    __syncthreads();

    // dir = 0: pred queries vs target refs; dir = 1: reverse.
#pragma unroll
    for (int dir = 0; dir < 2; dir++) {
        int nq = dir ? ntt : np;
        int nr4 = dir ? np4 : nt4;
        const float* qx = dir ? stx : spx;
        const float* qy = dir ? sty : spy;
        const float* rx = dir ? spx : stx;
        const float* ry = dir ? spy : sty;
        const float* rq = dir ? sqp : sqt;
        for (int base = 0; base < nq; base += 512) {
            int iq = base + tid;
            bool act = iq < nq;
            float x = act ? qx[iq] : 0.f, y = act ? qy[iq] : 0.f;
            float nx = -2.f * x, ny = -2.f * y;
            float xx = fmaf(x, x, y * y);
            float m = act ? 3.4e38f : -3.4e38f;
            for (int j = 0; j < nr4; j += 4) {
                const float4 t4 = *reinterpret_cast<const float4*>(&rx[j]);
                const float4 y4 = *reinterpret_cast<const float4*>(&ry[j]);
                const float4 q4 = *reinterpret_cast<const float4*>(&rq[j]);
                m = fminf(m, fmaf(t4.x, nx, fmaf(y4.x, ny, q4.x)));
                m = fminf(m, fmaf(t4.y, nx, fmaf(y4.y, ny, q4.y)));
                m = fminf(m, fmaf(t4.z, nx, fmaf(y4.z, ny, q4.z)));
                m = fminf(m, fmaf(t4.w, nx, fmaf(y4.w, ny, q4.w)));
                if ((j & 127) == 124) {      // every 32 chunks = 128 refs
                    float bestd2 = __uint_as_float(*(volatile unsigned int*)&s_best);
                    if (__all_sync(0xffffffffu, m <= bestd2 - xx)) break;
                }
            }
            if (act) {
                float d2 = fmaxf(m + xx, 0.0f);
                atomicMax(&s_best, __float_as_uint(d2));
            }
            __syncthreads();                 // publish best to next wave
        }
    }
    if (tid == 0) {
        float diag = sqrtf((float)(HDIM * HDIM + WDIM * WDIM));
        float hd = sqrtf(__uint_as_float(s_best)) / diag;
        g_hd[b] = fminf(fmaxf(hd, 0.0f), 0.1f);
        __threadfence();
        unsigned int old = atomicAdd(&g_done, 1u);
        s_last = (old == BATCH - 1);
    }
    __syncthreads();
    if (s_last && tid == 0) {
        __threadfence();
        float ssum = 0.0f;
        for (int i = 0; i < BATCH; i++) ssum += g_hd[i];
        out[0] = ssum / (float)BATCH;
    }
}

// ---------------- launch ----------------
extern "C" void kernel_launch(void* const* d_in, const int* in_sizes, int n_in,
                              void* d_out, int out_size) {
    const float* pred   = (const float*)d_in[0];
    const float* target = (const float*)d_in[1];
    float* out = (float*)d_out;

    k_init<<<1, 256>>>();                    // idx 0
    k_fused<<<NIMG * 64, 256>>>(pred, target); // idx 1
    k_sort_emit<<<NIMG, 512>>>();            // idx 2
    k_hd_mean<<<BATCH, 512>>>(out);          // idx 3  (ncu samples here)
}

// round 7
// speedup vs baseline: 1.1526x; 1.1526x over previous
#include <cuda_runtime.h>
#include <cuda_bf16.h>
#include <stdint.h>

// ---------------- problem constants ----------------
#define BATCH   64
#define HDIM    512
#define WDIM    512
#define NPIX    (HDIM*WDIM)          // 262144
#define NWORDS  (NPIX/32)
#define NIMG    (2*BATCH)            // 128
#define NPTS    1000
#define NPTS4   1004
#define CANDCAP 4096
#define PARTS   4
#define HDBLOCKS (BATCH*2*PARTS)     // 512
#define UTH     0.99277f             // E[accepted] ~ 0.00723*nvalid

// ---------------- device scratch ----------------
__device__ uint32_t g_keys[256];
__device__ uint32_t g_validbits[NIMG*NWORDS];
__device__ uint32_t g_nvalid[NIMG];
__device__ uint32_t g_candcnt[NIMG];
__device__ unsigned long long g_cand[(size_t)NIMG*CANDCAP];
__device__ float    g_lx[NIMG*NPTS4];
__device__ float    g_ly[NIMG*NPTS4];
__device__ float    g_q [NIMG*NPTS4];
__device__ int      g_np[NIMG];
__device__ unsigned int g_hdbits[BATCH];
__device__ unsigned int g_done;

// ---------------- threefry2x32 (JAX partitionable semantics) ----------------
__device__ __forceinline__ uint32_t rotl32(uint32_t x, int r) {
    return __funnelshift_l(x, x, r);
}
__device__ __forceinline__ void threefry2x32(uint32_t k0, uint32_t k1,
                                             uint32_t x0, uint32_t x1,
                                             uint32_t& o0, uint32_t& o1) {
    uint32_t ks2 = k0 ^ k1 ^ 0x1BD11BDAu;
    x0 += k0; x1 += k1;
#define TF_RND(r) { x0 += x1; x1 = rotl32(x1, r); x1 ^= x0; }
    TF_RND(13) TF_RND(15) TF_RND(26) TF_RND(6)   x0 += k1;  x1 += ks2 + 1u;
    TF_RND(17) TF_RND(29) TF_RND(16) TF_RND(24)  x0 += ks2; x1 += k0  + 2u;
    TF_RND(13) TF_RND(15) TF_RND(26) TF_RND(6)   x0 += k0;  x1 += k1  + 3u;
    TF_RND(17) TF_RND(29) TF_RND(16) TF_RND(24)  x0 += k1;  x1 += ks2 + 4u;
    TF_RND(13) TF_RND(15) TF_RND(26) TF_RND(6)   x0 += ks2; x1 += k0  + 5u;
#undef TF_RND
    o0 = x0; o1 = x1;
}
__device__ __forceinline__ float bits_to_uniform(uint32_t bits) {
    return __uint_as_float((bits >> 9) | 0x3F800000u) - 1.0f;
}

// ---------------- kernels ----------------
__global__ void k_init() {
    int i = threadIdx.x;
    if (i < NIMG) { g_candcnt[i] = 0u; g_nvalid[i] = 0u; }
    if (i < BATCH) g_hdbits[i] = 0u;
    if (i == 0)   g_done = 0u;
    if (i < 128) {
        uint32_t o0, o1;
        threefry2x32(0u, 1u, 0u, (uint32_t)i, o0, o1);
        g_keys[2*i] = o0; g_keys[2*i + 1] = o1;
    }
}

// Fused: tiled Sobel (sigmoid fused for pred) + threefry + threshold accept.
__global__ void __launch_bounds__(256) k_fused(const float* __restrict__ pred,
                                               const float* __restrict__ target) {
    __shared__ float s[10][514];
    __shared__ unsigned int blkcnt;
    int bx  = blockIdx.x;
    int b   = bx >> 6;
    int r0  = (bx & 63) << 3;
    int tid = threadIdx.x;
    if (tid == 0) blkcnt = 0u;
    bool isPred = (b < BATCH);
    const float* src = isPred ? (pred + (size_t)b * NPIX)
                              : (target + (size_t)(b - BATCH) * NPIX);
    for (int idx = tid; idx < 1280; idx += 256) {
        int lr = idx >> 7;
        int c4 = (idx & 127) << 2;
        int gr = r0 + lr - 1;
        float4 v;
        if (gr >= 0 && gr < HDIM) {
            v = *reinterpret_cast<const float4*>(src + ((size_t)gr << 9) + c4);
            if (isPred) {
                v.x = 1.0f / (1.0f + expf(-v.x));
                v.y = 1.0f / (1.0f + expf(-v.y));
                v.z = 1.0f / (1.0f + expf(-v.z));
                v.w = 1.0f / (1.0f + expf(-v.w));
            }
        } else v = make_float4(0.f, 0.f, 0.f, 0.f);
        s[lr][1 + c4] = v.x; s[lr][2 + c4] = v.y;
        s[lr][3 + c4] = v.z; s[lr][4 + c4] = v.w;
        if (c4 == 0) { s[lr][0] = 0.f; s[lr][513] = 0.f; }
    }
    __syncthreads();
    uint32_t k0 = g_keys[2*b], k1 = g_keys[2*b + 1];
    int w = tid >> 5, lane = tid & 31;
    unsigned int myc = 0;
    for (int u = w; u < 128; u += 8) {
        int row8 = u >> 4, seg = u & 15;
        int sc = seg * 32 + lane + 1;
        float L0 = s[row8  ][sc-1], M0 = s[row8  ][sc], R0 = s[row8  ][sc+1];
        float L1 = s[row8+1][sc-1],                     R1 = s[row8+1][sc+1];
        float L2 = s[row8+2][sc-1], M2 = s[row8+2][sc], R2 = s[row8+2][sc+1];
        float gx = (R0 - L0) + 2.0f * (R1 - L1) + (R2 - L2);
        float gy = (L2 + 2.0f * M2 + R2) - (L0 + 2.0f * M0 + R0);
        float bm = sqrtf(gx * gx + gy * gy + 1e-8f);
        bool v = bm > 0.1f;
        int gr = r0 + row8;
        unsigned int word = __ballot_sync(0xffffffffu, v);
        if (lane == 0) {
            g_validbits[b * NWORDS + gr * 16 + seg] = word;
            myc += __popc(word);
        }
        int i = (gr << 9) + seg * 32 + lane;
        uint32_t o0, o1;
        threefry2x32(k0, k1, 0u, (uint32_t)i, o0, o1);
        float uu = bits_to_uniform(o0 ^ o1);
        bool acc = v && (uu > UTH);
        unsigned int amask = __ballot_sync(0xffffffffu, acc);
        if (amask) {
            int leader = __ffs(amask) - 1;
            uint32_t base = 0;
            if (lane == leader) base = atomicAdd(&g_candcnt[b], (uint32_t)__popc(amask));
            base = __shfl_sync(0xffffffffu, base, leader);
            if (acc) {
                uint32_t pos = base + __popc(amask & ((1u << lane) - 1u));
                if (pos < CANDCAP) {
                    uint32_t sb = __float_as_uint(2.0f + uu);
                    g_cand[(size_t)b * CANDCAP + pos] =
                        (((unsigned long long)sb) << 32) | (unsigned long long)(~(uint32_t)i);
                }
            }
        }
    }
    if (lane == 0 && myc) atomicAdd(&blkcnt, myc);
    __syncthreads();
    if (tid == 0 && blkcnt) atomicAdd(&g_nvalid[b], blkcnt);
}

// Sort + emit (rescue slow path inlined; never taken on sane inputs).
__global__ void __launch_bounds__(512) k_sort_emit() {
    __shared__ unsigned long long s[CANDCAP];
    __shared__ unsigned int rc;
    int b = blockIdx.x, tid = threadIdx.x, nt = blockDim.x;
    unsigned int cnt = g_candcnt[b]; if (cnt > CANDCAP) cnt = CANDCAP;
    unsigned int nv = g_nvalid[b];
    unsigned int needed = (nv < (unsigned)NPTS) ? nv : (unsigned)NPTS;
    if (cnt < needed) {
        // RESCUE: recompute with adaptive tau (guaranteed coverage)
        if (tid == 0) rc = 0u;
        __syncthreads();
        uint32_t k0 = g_keys[2*b], k1 = g_keys[2*b + 1];
        uint32_t tau = 0u;
        if (nv > 2500u)
            tau = __float_as_uint(2.0f + (1.0f - 2048.0f / (float)nv));
        int lane = tid & 31;
        for (int i = tid; i < NPIX; i += nt) {
            uint32_t vw = g_validbits[b * NWORDS + (i >> 5)];
            bool v = (vw >> lane) & 1u;
            uint32_t o0, o1;
            threefry2x32(k0, k1, 0u, (uint32_t)i, o0, o1);
            uint32_t sb = __float_as_uint(2.0f + bits_to_uniform(o0 ^ o1));
            bool acc = v && (sb >= tau);
            unsigned int amask = __ballot_sync(0xffffffffu, acc);
            if (amask) {
                int leader = __ffs(amask) - 1;
                uint32_t base = 0;
                if (lane == leader) base = atomicAdd(&rc, (uint32_t)__popc(amask));
                base = __shfl_sync(0xffffffffu, base, leader);
                if (acc) {
                    uint32_t pos = base + __popc(amask & ((1u << lane) - 1u));
                    if (pos < CANDCAP)
                        s[pos] = (((unsigned long long)sb) << 32)
                               | (unsigned long long)(~(uint32_t)i);
                }
            }
        }
        __syncthreads();
        cnt = rc; if (cnt > CANDCAP) cnt = CANDCAP;
    } else {
        for (unsigned int i = tid; i < cnt; i += nt)
            s[i] = g_cand[(size_t)b * CANDCAP + i];
    }
    int n = 2; while (n < (int)cnt) n <<= 1;
    for (int i = (int)cnt + tid; i < n; i += nt) s[i] = 0ull;   // pad
    __syncthreads();
    for (int k = 2; k <= n; k <<= 1) {
        for (int j = k >> 1; j > 0; j >>= 1) {
            for (int i = tid; i < n; i += nt) {
                int ixj = i ^ j;
                if (ixj > i) {
                    unsigned long long a = s[i], bb = s[ixj];
                    if ((a > bb) == ((i & k) == 0)) { s[i] = bb; s[ixj] = a; }
                }
            }
            __syncthreads();
        }
    }
    int need = (cnt < (unsigned)NPTS) ? (int)cnt : NPTS;
    int npts = (cnt == 0u) ? 1 : need;
    int pad  = (npts + 3) & ~3;
    for (int j = tid; j < pad; j += nt) {
        float x, y, q;
        if (j < npts) {
            if (cnt == 0u) { x = 256.0f; y = 256.0f; }
            else {
                unsigned long long key = s[n - 1 - j];
                uint32_t idx = ~(uint32_t)key;
                x = (float)(idx >> 9); y = (float)(idx & 511);
            }
            q = x * x + y * y;
        } else { x = 0.0f; y = 0.0f; q = 3.0e38f; }   // sentinel
        g_lx[b * NPTS4 + j] = x;
        g_ly[b * NPTS4 + j] = y;
        g_q [b * NPTS4 + j] = q;
    }
    if (tid == 0) g_np[b] = npts;
}

// Hausdorff: 512 blocks = 64 images x 2 directions x 4 query parts.
// Refs in smem (12KB), queries register-resident; min-tree inner loop.
// All d^2 exact integers in fp32 -> atomicMax on float bits is exact.
__global__ void __launch_bounds__(256) k_hd_mean(float* __restrict__ out) {
    __shared__ __align__(16) float rx[NPTS4], ry[NPTS4], rq[NPTS4];
    __shared__ int s_last;
    int blk  = blockIdx.x;
    int b    = blk >> 3;
    int dir  = (blk >> 2) & 1;
    int part = blk & 3;
    int tid  = threadIdx.x;
    int qimg = dir ? (BATCH + b) : b;
    int rimg = dir ? b : (BATCH + b);
    int nq = g_np[qimg];
    int nr4 = (g_np[rimg] + 3) & ~3;
    if (tid == 0) s_last = 0;
    for (int i = tid; i < nr4; i += 256) {
        rx[i] = g_lx[rimg * NPTS4 + i];
        ry[i] = g_ly[rimg * NPTS4 + i];
        rq[i] = g_q [rimg * NPTS4 + i];
    }
    __syncthreads();
    int ch = (nq + PARTS - 1) / PARTS;
    int i0 = part * ch;
    int i1 = (i0 + ch < nq) ? (i0 + ch) : nq;
    int iq = i0 + tid;
    float lmax = 0.0f;
    if (iq < i1) {
        float x = g_lx[qimg * NPTS4 + iq];
        float y = g_ly[qimg * NPTS4 + iq];
        float nx = -2.0f * x, ny = -2.0f * y;
        float xx = fmaf(x, x, y * y);
        float m = 3.4e38f;
#pragma unroll 4
        for (int j = 0; j < nr4; j += 4) {
            const float4 t4 = *reinterpret_cast<const float4*>(&rx[j]);
            const float4 y4 = *reinterpret_cast<const float4*>(&ry[j]);
            const float4 q4 = *reinterpret_cast<const float4*>(&rq[j]);
            float c0 = fmaf(t4.x, nx, fmaf(y4.x, ny, q4.x));
            float c1 = fmaf(t4.y, nx, fmaf(y4.y, ny, q4.y));
            float c2 = fmaf(t4.z, nx, fmaf(y4.z, ny, q4.z));
            float c3 = fmaf(t4.w, nx, fmaf(y4.w, ny, q4.w));
            m = fminf(m, fminf(fminf(c0, c1), fminf(c2, c3)));
        }
        lmax = fmaxf(m + xx, 0.0f);          // d^2, exact
    }
    // block-reduce max then one global atomic
    __shared__ float red[8];
    for (int off = 16; off; off >>= 1)
        lmax = fmaxf(lmax, __shfl_down_sync(0xffffffffu, lmax, off));
    if ((tid & 31) == 0) red[tid >> 5] = lmax;
    __syncthreads();
    if (tid < 32) {
        float vv = (tid < 8) ? red[tid] : 0.0f;
        for (int off = 4; off; off >>= 1)
            vv = fmaxf(vv, __shfl_down_sync(0xffffffffu, vv, off));
        if (tid == 0) {
            atomicMax(&g_hdbits[b], __float_as_uint(vv));
            __threadfence();
            unsigned int old = atomicAdd(&g_done, 1u);
            s_last = (old == HDBLOCKS - 1);
        }
    }
    __syncthreads();
    if (s_last && tid == 0) {
        __threadfence();
        float diag = sqrtf((float)(HDIM * HDIM + WDIM * WDIM));
        float ssum = 0.0f;
        for (int i = 0; i < BATCH; i++) {
            float hd = sqrtf(__uint_as_float(g_hdbits[i])) / diag;
            ssum += fminf(fmaxf(hd, 0.0f), 0.1f);
        }
        out[0] = ssum / (float)BATCH;
    }
}

// ---------------- launch ----------------
extern "C" void kernel_launch(void* const* d_in, const int* in_sizes, int n_in,
                              void* d_out, int out_size) {
    const float* pred   = (const float*)d_in[0];
    const float* target = (const float*)d_in[1];
    float* out = (float*)d_out;

    k_init<<<1, 256>>>();                      // idx 0
    k_fused<<<NIMG * 64, 256>>>(pred, target); // idx 1
    k_sort_emit<<<NIMG, 512>>>();              // idx 2
    k_hd_mean<<<HDBLOCKS, 256>>>(out);         // idx 3 (ncu samples here)
}

// round 8
// speedup vs baseline: 1.2422x; 1.0778x over previous
#include <cuda_runtime.h>
#include <cuda_bf16.h>
#include <stdint.h>

// ---------------- problem constants ----------------
#define BATCH   64
#define HDIM    512
#define WDIM    512
#define NPIX    (HDIM*WDIM)          // 262144
#define NWORDS  (NPIX/32)
#define NIMG    (2*BATCH)            // 128
#define NPTS    1000
#define NPTSP   1008                 // padded stride (mult of 8 + sentinels)
#define CANDCAP 4096
#define PARTS   8
#define HDBLOCKS (BATCH*2*PARTS)     // 1024
#define BNDCAP  1024
#define UTH     0.99277f             // E[accepted] ~ 0.00723*nvalid

// ---------------- device scratch (zero-initialized; self-cleaning) ----------------
__device__ uint32_t g_validbits[NIMG*NWORDS];
__device__ uint32_t g_nvalid[NIMG];
__device__ uint32_t g_candcnt[NIMG];
__device__ unsigned long long g_cand[(size_t)NIMG*CANDCAP];
__device__ float    g_lx[NIMG*NPTSP];
__device__ float    g_ly[NIMG*NPTSP];
__device__ float    g_q [NIMG*NPTSP];
__device__ int      g_np[NIMG];
__device__ unsigned int g_hdbits[BATCH];
__device__ unsigned int g_done;

// ---------------- threefry2x32 (JAX partitionable semantics) ----------------
__device__ __forceinline__ uint32_t rotl32(uint32_t x, int r) {
    return __funnelshift_l(x, x, r);
}
__device__ __forceinline__ void threefry2x32(uint32_t k0, uint32_t k1,
                                             uint32_t x0, uint32_t x1,
                                             uint32_t& o0, uint32_t& o1) {
    uint32_t ks2 = k0 ^ k1 ^ 0x1BD11BDAu;
    x0 += k0; x1 += k1;
#define TF_RND(r) { x0 += x1; x1 = rotl32(x1, r); x1 ^= x0; }
    TF_RND(13) TF_RND(15) TF_RND(26) TF_RND(6)   x0 += k1;  x1 += ks2 + 1u;
    TF_RND(17) TF_RND(29) TF_RND(16) TF_RND(24)  x0 += ks2; x1 += k0  + 2u;
    TF_RND(13) TF_RND(15) TF_RND(26) TF_RND(6)   x0 += k0;  x1 += k1  + 3u;
    TF_RND(17) TF_RND(29) TF_RND(16) TF_RND(24)  x0 += k1;  x1 += ks2 + 4u;
    TF_RND(13) TF_RND(15) TF_RND(26) TF_RND(6)   x0 += ks2; x1 += k0  + 5u;
#undef TF_RND
    o0 = x0; o1 = x1;
}
__device__ __forceinline__ float bits_to_uniform(uint32_t bits) {
    return __uint_as_float((bits >> 9) | 0x3F800000u) - 1.0f;
}
// partitionable split(key(1),128): key_b = threefry((0,1), (0,b))
__device__ __forceinline__ void image_key(int b, uint32_t& k0, uint32_t& k1) {
    threefry2x32(0u, 1u, 0u, (uint32_t)b, k0, k1);
}

// ---------------- k_fused: Sobel(+sigmoid) + threefry + threshold accept ------
__global__ void __launch_bounds__(256) k_fused(const float* __restrict__ pred,
                                               const float* __restrict__ target) {
    __shared__ float s[10][514];
    __shared__ unsigned int blkcnt;
    __shared__ uint32_t skey[2];
    int bx  = blockIdx.x;
    int b   = bx >> 6;
    int r0  = (bx & 63) << 3;
    int tid = threadIdx.x;
    if (tid == 0) blkcnt = 0u;
    bool isPred = (b < BATCH);
    const float* src = isPred ? (pred + (size_t)b * NPIX)
                              : (target + (size_t)(b - BATCH) * NPIX);
    for (int idx = tid; idx < 1280; idx += 256) {
        int lr = idx >> 7;
        int c4 = (idx & 127) << 2;
        int gr = r0 + lr - 1;
        float4 v;
        if (gr >= 0 && gr < HDIM) {
            v = *reinterpret_cast<const float4*>(src + ((size_t)gr << 9) + c4);
            if (isPred) {
                v.x = 1.0f / (1.0f + expf(-v.x));
                v.y = 1.0f / (1.0f + expf(-v.y));
                v.z = 1.0f / (1.0f + expf(-v.z));
                v.w = 1.0f / (1.0f + expf(-v.w));
            }
        } else v = make_float4(0.f, 0.f, 0.f, 0.f);
        s[lr][1 + c4] = v.x; s[lr][2 + c4] = v.y;
        s[lr][3 + c4] = v.z; s[lr][4 + c4] = v.w;
        if (c4 == 0) { s[lr][0] = 0.f; s[lr][513] = 0.f; }
    }
    if (tid < 32) {                      // warp 0 computes the image key
        uint32_t a, c;
        image_key(b, a, c);
        if (tid == 0) { skey[0] = a; skey[1] = c; }
    }
    __syncthreads();
    uint32_t k0 = skey[0], k1 = skey[1];
    int w = tid >> 5, lane = tid & 31;
    unsigned int myc = 0;
    for (int u = w; u < 128; u += 8) {
        int row8 = u >> 4, seg = u & 15;
        int sc = seg * 32 + lane + 1;
        float L0 = s[row8  ][sc-1], M0 = s[row8  ][sc], R0 = s[row8  ][sc+1];
        float L1 = s[row8+1][sc-1],                     R1 = s[row8+1][sc+1];
        float L2 = s[row8+2][sc-1], M2 = s[row8+2][sc], R2 = s[row8+2][sc+1];
        float gx = (R0 - L0) + 2.0f * (R1 - L1) + (R2 - L2);
        float gy = (L2 + 2.0f * M2 + R2) - (L0 + 2.0f * M0 + R0);
        float bm = sqrtf(gx * gx + gy * gy + 1e-8f);
        bool v = bm > 0.1f;
        int gr = r0 + row8;
        unsigned int word = __ballot_sync(0xffffffffu, v);
        if (lane == 0) {
            g_validbits[b * NWORDS + gr * 16 + seg] = word;
            myc += __popc(word);
        }
        int i = (gr << 9) + seg * 32 + lane;
        uint32_t o0, o1;
        threefry2x32(k0, k1, 0u, (uint32_t)i, o0, o1);
        float uu = bits_to_uniform(o0 ^ o1);
        bool acc = v && (uu > UTH);
        unsigned int amask = __ballot_sync(0xffffffffu, acc);
        if (amask) {
            int leader = __ffs(amask) - 1;
            uint32_t base = 0;
            if (lane == leader) base = atomicAdd(&g_candcnt[b], (uint32_t)__popc(amask));
            base = __shfl_sync(0xffffffffu, base, leader);
            if (acc) {
                uint32_t pos = base + __popc(amask & ((1u << lane) - 1u));
                if (pos < CANDCAP) {
                    uint32_t sb = __float_as_uint(2.0f + uu);
                    g_cand[(size_t)b * CANDCAP + pos] =
                        (((unsigned long long)sb) << 32) | (unsigned long long)(~(uint32_t)i);
                }
            }
        }
    }
    if (lane == 0 && myc) atomicAdd(&blkcnt, myc);
    __syncthreads();
    if (tid == 0 && blkcnt) atomicAdd(&g_nvalid[b], blkcnt);
}

// ---------------- k_select_emit: histogram top-k selection (exact tie-break) --
// One 256-thread block per image. Emission order is irrelevant for Hausdorff.
__global__ void __launch_bounds__(256) k_select_emit() {
    __shared__ uint32_t hist[4096];
    __shared__ uint32_t tsum[256];
    __shared__ uint32_t esuf[256];
    __shared__ unsigned long long bnd[BNDCAP];
    __shared__ unsigned int s_rc, s_emit, s_bcnt, s_C, s_G;
    int b = blockIdx.x, tid = threadIdx.x;
    unsigned int cnt = g_candcnt[b]; if (cnt > CANDCAP) cnt = CANDCAP;
    unsigned int nv  = g_nvalid[b];
    unsigned int needed = (nv < (unsigned)NPTS) ? nv : (unsigned)NPTS;

    if (cnt < needed) {
        // RESCUE (adaptive tau; statistically never taken on sane inputs)
        if (tid == 0) s_rc = 0u;
        __syncthreads();
        uint32_t k0, k1; image_key(b, k0, k1);
        uint32_t tau = 0u;
        if (nv > 2500u)
            tau = __float_as_uint(2.0f + (1.0f - 2048.0f / (float)nv));
        int lane = tid & 31;
        for (int i = tid; i < NPIX; i += 256) {
            uint32_t vw = g_validbits[b * NWORDS + (i >> 5)];
            bool v = (vw >> lane) & 1u;
            uint32_t o0, o1;
            threefry2x32(k0, k1, 0u, (uint32_t)i, o0, o1);
            uint32_t sb = __float_as_uint(2.0f + bits_to_uniform(o0 ^ o1));
            bool acc = v && (sb >= tau);
            unsigned int amask = __ballot_sync(0xffffffffu, acc);
            if (amask) {
                int leader = __ffs(amask) - 1;
                uint32_t base = 0;
                if (lane == leader) base = atomicAdd(&s_rc, (uint32_t)__popc(amask));
                base = __shfl_sync(0xffffffffu, base, leader);
                if (acc) {
                    uint32_t pos = base + __popc(amask & ((1u << lane) - 1u));
                    if (pos < CANDCAP)
                        g_cand[(size_t)b * CANDCAP + pos] =
                            (((unsigned long long)sb) << 32)
                          | (unsigned long long)(~(uint32_t)i);
                }
            }
        }
        __syncthreads();
        cnt = s_rc; if (cnt > CANDCAP) cnt = CANDCAP;
    }
    if (needed > cnt) needed = cnt;

    int npts;
    if (cnt == 0u) {
        npts = 1;
        if (tid == 0) {
            g_lx[b * NPTSP] = 256.0f;
            g_ly[b * NPTSP] = 256.0f;
            g_q [b * NPTSP] = 256.0f * 256.0f * 2.0f;
        }
    } else {
        npts = (int)needed;
        // ---- pass 1: histogram of score bits (bins monotone in sb) ----
        for (int k = tid; k < 4096; k += 256) hist[k] = 0u;
        if (tid == 0) { s_emit = 0u; s_bcnt = 0u; }
        __syncthreads();
        for (unsigned int i = tid; i < cnt; i += 256) {
            uint32_t sb = (uint32_t)(g_cand[(size_t)b * CANDCAP + i] >> 32);
            atomicAdd(&hist[(sb - 0x40000000u) >> 10], 1u);
        }
        __syncthreads();
        // ---- suffix scan to find cutoff bin C and G = count above C ----
        {
            uint32_t ls = 0;
            int base = tid * 16;
            for (int k = 0; k < 16; k++) ls += hist[base + k];
            tsum[tid] = ls;
        }
        __syncthreads();
        if (tid < 32) {
            uint32_t g = 0;
            for (int k = 0; k < 8; k++) g += tsum[tid * 8 + k];
            uint32_t sfx = g;
            for (int off = 1; off < 32; off <<= 1) {
                uint32_t o = __shfl_down_sync(0xffffffffu, sfx, off);
                if (tid + off < 32) sfx += o;
            }
            uint32_t cum = sfx - g;               // sum of groups after this one
            for (int k = 7; k >= 0; k--) {
                esuf[tid * 8 + k] = cum;
                cum += tsum[tid * 8 + k];
            }
        }
        __syncthreads();
        {
            uint32_t sa = esuf[tid];
            if (sa < needed && sa + tsum[tid] >= needed) {
                uint32_t cum = sa;
                for (int bin = tid * 16 + 15; ; bin--) {
                    uint32_t h = hist[bin];
                    if (cum + h >= needed) { s_C = (unsigned)bin; s_G = cum; break; }
                    cum += h;
                }
            }
        }
        __syncthreads();
        unsigned int C = s_C, G = s_G;
        // ---- pass 2: emit above-cutoff (any order); gather boundary bin ----
        for (unsigned int i = tid; i < cnt; i += 256) {
            unsigned long long key = g_cand[(size_t)b * CANDCAP + i];
            uint32_t sb = (uint32_t)(key >> 32);
            unsigned int bin = (sb - 0x40000000u) >> 10;
            if (bin > C) {
                unsigned int pos = atomicAdd(&s_emit, 1u);
                uint32_t idx = ~(uint32_t)key;
                float x = (float)(idx >> 9), y = (float)(idx & 511);
                g_lx[b * NPTSP + pos] = x;
                g_ly[b * NPTSP + pos] = y;
                g_q [b * NPTSP + pos] = x * x + y * y;
            } else if (bin == C) {
                unsigned int p = atomicAdd(&s_bcnt, 1u);
                if (p < BNDCAP) bnd[p] = key;
            }
        }
        __syncthreads();
        // ---- pass 3: sort boundary bin desc by full key, take needed-G ----
        unsigned int bcnt = s_bcnt; if (bcnt > BNDCAP) bcnt = BNDCAP;
        int n2 = 2; while (n2 < (int)bcnt) n2 <<= 1;
        for (int i = (int)bcnt + tid; i < n2; i += 256) bnd[i] = 0ull;
        __syncthreads();
        for (int k = 2; k <= n2; k <<= 1) {
            for (int j = k >> 1; j > 0; j >>= 1) {
                for (int i = tid; i < n2; i += 256) {
                    int ixj = i ^ j;
                    if (ixj > i) {
                        unsigned long long a = bnd[i], bb = bnd[ixj];
                        if ((a < bb) == ((i & k) == 0)) { bnd[i] = bb; bnd[ixj] = a; }
                    }
                }
                __syncthreads();
            }
        }
        unsigned int take = needed - G;
        for (unsigned int j = tid; j < take; j += 256) {
            uint32_t idx = ~(uint32_t)bnd[j];
            float x = (float)(idx >> 9), y = (float)(idx & 511);
            unsigned int pos = G + j;
            g_lx[b * NPTSP + pos] = x;
            g_ly[b * NPTSP + pos] = y;
            g_q [b * NPTSP + pos] = x * x + y * y;
        }
    }
    __syncthreads();
    // sentinels to next multiple of 8
    int pad = (npts + 7) & ~7;
    for (int j = npts + tid; j < pad; j += 256) {
        g_lx[b * NPTSP + j] = 0.0f;
        g_ly[b * NPTSP + j] = 0.0f;
        g_q [b * NPTSP + j] = 3.0e38f;
    }
    if (tid == 0) {
        g_np[b] = npts;
        g_candcnt[b] = 0u;       // self-clean for next graph replay
        g_nvalid[b]  = 0u;
    }
}

// ---------------- k_hd_mean: 1024 blocks = 64 img x 2 dir x 8 parts ----------
__global__ void __launch_bounds__(128) k_hd_mean(float* __restrict__ out) {
    __shared__ __align__(16) float rx[NPTSP], ry[NPTSP], rq[NPTSP];
    __shared__ float red[4];
    __shared__ int s_last;
    int blk  = blockIdx.x;
    int b    = blk >> 4;
    int dir  = (blk >> 3) & 1;
    int part = blk & 7;
    int tid  = threadIdx.x;
    int qimg = dir ? (BATCH + b) : b;
    int rimg = dir ? b : (BATCH + b);
    int nq  = g_np[qimg];
    int nr8 = (g_np[rimg] + 7) & ~7;
    if (tid == 0) s_last = 0;
    for (int i = tid; i < nr8; i += 128) {
        rx[i] = g_lx[rimg * NPTSP + i];
        ry[i] = g_ly[rimg * NPTSP + i];
        rq[i] = g_q [rimg * NPTSP + i];
    }
    __syncthreads();
    int ch = (nq + PARTS - 1) / PARTS;
    int i0 = part * ch;
    int i1 = (i0 + ch < nq) ? (i0 + ch) : nq;
    float lmax = 0.0f;
    for (int iq = i0 + tid; iq < i1; iq += 128) {
        float x = g_lx[qimg * NPTSP + iq];
        float y = g_ly[qimg * NPTSP + iq];
        float nx = -2.0f * x, ny = -2.0f * y;
        float xx = fmaf(x, x, y * y);
        float m0 = 3.4e38f, m1 = 3.4e38f;
        for (int j = 0; j < nr8; j += 8) {
            const float4 ta = *reinterpret_cast<const float4*>(&rx[j]);
            const float4 ya = *reinterpret_cast<const float4*>(&ry[j]);
            const float4 qa = *reinterpret_cast<const float4*>(&rq[j]);
            const float4 tb = *reinterpret_cast<const float4*>(&rx[j + 4]);
            const float4 yb = *reinterpret_cast<const float4*>(&ry[j + 4]);
            const float4 qb = *reinterpret_cast<const float4*>(&rq[j + 4]);
            float a0 = fmaf(ta.x, nx, fmaf(ya.x, ny, qa.x));
            float a1 = fmaf(ta.y, nx, fmaf(ya.y, ny, qa.y));
            float a2 = fmaf(ta.z, nx, fmaf(ya.z, ny, qa.z));
            float a3 = fmaf(ta.w, nx, fmaf(ya.w, ny, qa.w));
            float b0 = fmaf(tb.x, nx, fmaf(yb.x, ny, qb.x));
            float b1 = fmaf(tb.y, nx, fmaf(yb.y, ny, qb.y));
            float b2 = fmaf(tb.z, nx, fmaf(yb.z, ny, qb.z));
            float b3 = fmaf(tb.w, nx, fmaf(yb.w, ny, qb.w));
            m0 = fminf(m0, fminf(fminf(a0, a1), fminf(a2, a3)));
            m1 = fminf(m1, fminf(fminf(b0, b1), fminf(b2, b3)));
        }
        float m = fminf(m0, m1);
        lmax = fmaxf(lmax, fmaxf(m + xx, 0.0f));   // d^2, exact
    }
    for (int off = 16; off; off >>= 1)
        lmax = fmaxf(lmax, __shfl_down_sync(0xffffffffu, lmax, off));
    if ((tid & 31) == 0) red[tid >> 5] = lmax;
    __syncthreads();
    if (tid == 0) {
        float vv = fmaxf(fmaxf(red[0], red[1]), fmaxf(red[2], red[3]));
        atomicMax(&g_hdbits[b], __float_as_uint(vv));
        __threadfence();
        unsigned int old = atomicAdd(&g_done, 1u);
        s_last = (old == HDBLOCKS - 1);
    }
    __syncthreads();
    if (s_last && tid == 0) {
        __threadfence();
        float diag = sqrtf((float)(HDIM * HDIM + WDIM * WDIM));
        float ssum = 0.0f;
        for (int i = 0; i < BATCH; i++) {
            float hd = sqrtf(__uint_as_float(g_hdbits[i])) / diag;
            ssum += fminf(fmaxf(hd, 0.0f), 0.1f);
            g_hdbits[i] = 0u;                       // self-clean
        }
        out[0] = ssum / (float)BATCH;
        g_done = 0u;                                // self-clean
    }
}

// ---------------- launch ----------------
extern "C" void kernel_launch(void* const* d_in, const int* in_sizes, int n_in,
                              void* d_out, int out_size) {
    const float* pred   = (const float*)d_in[0];
    const float* target = (const float*)d_in[1];
    float* out = (float*)d_out;

    k_fused<<<NIMG * 64, 256>>>(pred, target);   // idx 0 (ncu: idx 3 = iter2's fused)
    k_select_emit<<<NIMG, 256>>>();              // idx 1
    k_hd_mean<<<HDBLOCKS, 128>>>(out);           // idx 2
}

// round 9
// speedup vs baseline: 1.2848x; 1.0343x over previous
#include <cuda_runtime.h>
#include <cuda_bf16.h>
#include <stdint.h>

// ---------------- problem constants ----------------
#define BATCH   64
#define HDIM    512
#define WDIM    512
#define NPIX    (HDIM*WDIM)          // 262144
#define NWORDS  (NPIX/32)
#define NIMG    (2*BATCH)            // 128
#define NPTS    1000
#define NPTSP   1008                 // padded stride (mult of 8 + sentinels)
#define CANDCAP 4096
#define PARTS   8
#define HDBLOCKS (BATCH*2*PARTS)     // 1024
#define BNDCAP  512
// integer acceptance threshold on (rb>>9): accept iff k >= KTH.
// E[cand] = (2^23 - KTH)/2^23 * nvalid ~ 0.00723 * nvalid ~ 1890.
#define KTH     8327961u

// ---------------- device scratch (zero-init; self-cleaning) ----------------
__device__ uint32_t g_validbits[NIMG*NWORDS];
__device__ uint32_t g_nvalid[NIMG];
__device__ uint32_t g_candcnt[NIMG];
__device__ uint32_t g_imgdone[NIMG];
__device__ unsigned long long g_cand[(size_t)NIMG*CANDCAP];
__device__ float    g_lx[NIMG*NPTSP];
__device__ float    g_ly[NIMG*NPTSP];
__device__ float    g_q [NIMG*NPTSP];
__device__ int      g_np[NIMG];
__device__ unsigned int g_hdbits[BATCH];
__device__ unsigned int g_done;

// ---------------- threefry2x32 (JAX partitionable semantics) ----------------
__device__ __forceinline__ uint32_t rotl32(uint32_t x, int r) {
    return __funnelshift_l(x, x, r);
}
__device__ __forceinline__ void threefry2x32(uint32_t k0, uint32_t k1,
                                             uint32_t x0, uint32_t x1,
                                             uint32_t& o0, uint32_t& o1) {
    uint32_t ks2 = k0 ^ k1 ^ 0x1BD11BDAu;
    x0 += k0; x1 += k1;
#define TF_RND(r) { x0 += x1; x1 = rotl32(x1, r); x1 ^= x0; }
    TF_RND(13) TF_RND(15) TF_RND(26) TF_RND(6)   x0 += k1;  x1 += ks2 + 1u;
    TF_RND(17) TF_RND(29) TF_RND(16) TF_RND(24)  x0 += ks2; x1 += k0  + 2u;
    TF_RND(13) TF_RND(15) TF_RND(26) TF_RND(6)   x0 += k0;  x1 += k1  + 3u;
    TF_RND(17) TF_RND(29) TF_RND(16) TF_RND(24)  x0 += k1;  x1 += ks2 + 4u;
    TF_RND(13) TF_RND(15) TF_RND(26) TF_RND(6)   x0 += ks2; x1 += k0  + 5u;
#undef TF_RND
    o0 = x0; o1 = x1;
}
__device__ __forceinline__ float bits_to_uniform(uint32_t bits) {
    return __uint_as_float((bits >> 9) | 0x3F800000u) - 1.0f;
}
// partitionable split(key(1),128): key_b = threefry((0,1), (0,b))
__device__ __forceinline__ void image_key(int b, uint32_t& k0, uint32_t& k1) {
    threefry2x32(0u, 1u, 0u, (uint32_t)b, k0, k1);
}

__device__ __forceinline__ void emit_point(int b, unsigned int pos, uint32_t idx) {
    float x = (float)(idx >> 9), y = (float)(idx & 511);
    g_lx[b * NPTSP + pos] = x;
    g_ly[b * NPTSP + pos] = y;
    g_q [b * NPTSP + pos] = x * x + y * y;
}

// ---------------- selection (runs in the last-finishing block of an image) ---
__device__ __noinline__ void select_image(int b, uint32_t* hist,
                                          unsigned long long* bnd) {
    __shared__ uint32_t tsum[256];
    __shared__ uint32_t esuf[256];
    __shared__ unsigned int s_rc, s_emit, s_bcnt, s_C, s_G;
    int tid = threadIdx.x;
    unsigned int cnt = g_candcnt[b]; if (cnt > CANDCAP) cnt = CANDCAP;
    unsigned int nv  = g_nvalid[b];
    unsigned int needed = (nv < (unsigned)NPTS) ? nv : (unsigned)NPTS;
    bool rescued = false;
    if (cnt < needed) {
        // RESCUE: adaptive tau; statistically never taken.
        if (tid == 0) s_rc = 0u;
        __syncthreads();
        uint32_t k0, k1; image_key(b, k0, k1);
        uint32_t tau = 0u;
        if (nv > 2500u)
            tau = __float_as_uint(2.0f + (1.0f - 2048.0f / (float)nv));
        int lane = tid & 31;
        for (int i = tid; i < NPIX; i += 256) {
            uint32_t vw = g_validbits[b * NWORDS + (i >> 5)];
            bool v = (vw >> lane) & 1u;
            uint32_t o0, o1;
            threefry2x32(k0, k1, 0u, (uint32_t)i, o0, o1);
            uint32_t sb = __float_as_uint(2.0f + bits_to_uniform(o0 ^ o1));
            bool acc = v && (sb >= tau);
            unsigned int amask = __ballot_sync(0xffffffffu, acc);
            if (amask) {
                int leader = __ffs(amask) - 1;
                uint32_t base = 0;
                if (lane == leader) base = atomicAdd(&s_rc, (uint32_t)__popc(amask));
                base = __shfl_sync(0xffffffffu, base, leader);
                if (acc) {
                    uint32_t pos = base + __popc(amask & ((1u << lane) - 1u));
                    if (pos < CANDCAP)
                        g_cand[(size_t)b * CANDCAP + pos] =
                            (((unsigned long long)sb) << 32)
                          | (unsigned long long)(~(uint32_t)i);
                }
            }
        }
        __syncthreads();
        cnt = s_rc; if (cnt > CANDCAP) cnt = CANDCAP;
        rescued = true;
    }
    if (needed > cnt) needed = cnt;

    int npts;
    if (cnt == 0u) {
        npts = 1;
        if (tid == 0) {
            g_lx[b * NPTSP] = 256.0f;
            g_ly[b * NPTSP] = 256.0f;
            g_q [b * NPTSP] = 131072.0f;
        }
    } else if (cnt <= needed) {
        npts = (int)cnt;                      // take everything
        for (unsigned int i = tid; i < cnt; i += 256)
            emit_point(b, i, ~(uint32_t)g_cand[(size_t)b * CANDCAP + i]);
    } else {
        npts = (int)needed;
        const uint32_t SB = rescued ? 0x40000000u : 0x403F0000u;
        const int      SH = rescued ? 12 : 4;
        for (int k = tid; k < 4096; k += 256) hist[k] = 0u;
        if (tid == 0) { s_emit = 0u; s_bcnt = 0u; }
        __syncthreads();
        for (unsigned int i = tid; i < cnt; i += 256) {
            uint32_t sb = (uint32_t)(g_cand[(size_t)b * CANDCAP + i] >> 32);
            int bin = (int)((sb - SB) >> SH); if (bin > 4095) bin = 4095;
            atomicAdd(&hist[bin], 1u);
        }
        __syncthreads();
        {   // suffix scan for cutoff bin C, G = count above C
            uint32_t ls = 0;
            int base = tid * 16;
            for (int k = 0; k < 16; k++) ls += hist[base + k];
            tsum[tid] = ls;
        }
        __syncthreads();
        if (tid < 32) {
            uint32_t g = 0;
            for (int k = 0; k < 8; k++) g += tsum[tid * 8 + k];
            uint32_t sfx = g;
            for (int off = 1; off < 32; off <<= 1) {
                uint32_t o = __shfl_down_sync(0xffffffffu, sfx, off);
                if (tid + off < 32) sfx += o;
            }
            uint32_t cum = sfx - g;
            for (int k = 7; k >= 0; k--) {
                esuf[tid * 8 + k] = cum;
                cum += tsum[tid * 8 + k];
            }
        }
        __syncthreads();
        {
            uint32_t sa = esuf[tid];
            if (sa < needed && sa + tsum[tid] >= needed) {
                uint32_t cum = sa;
                for (int bin = tid * 16 + 15; ; bin--) {
                    uint32_t h = hist[bin];
                    if (cum + h >= needed) { s_C = (unsigned)bin; s_G = cum; break; }
                    cum += h;
                }
            }
        }
        __syncthreads();
        unsigned int C = s_C, G = s_G;
        for (unsigned int i = tid; i < cnt; i += 256) {
            unsigned long long key = g_cand[(size_t)b * CANDCAP + i];
            uint32_t sb = (uint32_t)(key >> 32);
            int bin = (int)((sb - SB) >> SH); if (bin > 4095) bin = 4095;
            if (bin > (int)C) {
                unsigned int pos = atomicAdd(&s_emit, 1u);
                emit_point(b, pos, ~(uint32_t)key);
            } else if (bin == (int)C) {
                unsigned int p = atomicAdd(&s_bcnt, 1u);
                if (p < BNDCAP) bnd[p] = key;
            }
        }
        __syncthreads();
        unsigned int bcnt = s_bcnt; if (bcnt > BNDCAP) bcnt = BNDCAP;
        int n2 = 2; while (n2 < (int)bcnt) n2 <<= 1;
        for (int i = (int)bcnt + tid; i < n2; i += 256) bnd[i] = 0ull;
        __syncthreads();
        for (int k = 2; k <= n2; k <<= 1) {           // sort desc by full key
            for (int j = k >> 1; j > 0; j >>= 1) {
                for (int i = tid; i < n2; i += 256) {
                    int ixj = i ^ j;
                    if (ixj > i) {
                        unsigned long long a = bnd[i], bb = bnd[ixj];
                        if ((a < bb) == ((i & k) == 0)) { bnd[i] = bb; bnd[ixj] = a; }
                    }
                }
                __syncthreads();
            }
        }
        unsigned int take = needed - G; if (take > bcnt) take = bcnt;
        for (unsigned int j = tid; j < take; j += 256)
            emit_point(b, G + j, ~(uint32_t)bnd[j]);
    }
    __syncthreads();
    int pad = (npts + 7) & ~7;                       // sentinels
    for (int j = npts + tid; j < pad; j += 256) {
        g_lx[b * NPTSP + j] = 0.0f;
        g_ly[b * NPTSP + j] = 0.0f;
        g_q [b * NPTSP + j] = 3.0e38f;
    }
    if (tid == 0) {
        g_np[b] = npts;
        g_candcnt[b] = 0u;     // self-clean for graph replay
        g_nvalid[b]  = 0u;
        g_imgdone[b] = 0u;
    }
}

// ---------------- k_fused: Sobel(+sigmoid) + threefry + accept + selection ---
__global__ void __launch_bounds__(256) k_fused(const float* __restrict__ pred,
                                               const float* __restrict__ target) {
    __shared__ __align__(16) unsigned char s_raw[20608];
    float (*s)[514] = reinterpret_cast<float(*)[514]>(s_raw);
    __shared__ unsigned int blkcnt;
    __shared__ uint32_t skey[2];
    __shared__ uint32_t s_tb;
    __shared__ int s_isLast;
    int bx  = blockIdx.x;
    int b   = bx >> 6;
    int r0  = (bx & 63) << 3;
    int tid = threadIdx.x;
    if (tid == 0) {
        blkcnt = 0u;
        // exact bits threshold T: z >= T  <=>  sqrtf(z) > 0.1f (sqrt.rn monotone)
        double mid = (double)0.1f + 3.7252902984619140625e-9;  // c + ulp/2, exact
        double T = mid * mid;                                  // exact (50 bits)
        float t1 = (float)T;
        uint32_t tb = __float_as_uint(t1);
        if ((double)t1 < T) tb++;
        s_tb = tb;
    }
    bool isPred = (b < BATCH);
    const float* src = isPred ? (pred + (size_t)b * NPIX)
                              : (target + (size_t)(b - BATCH) * NPIX);
    for (int idx = tid; idx < 1280; idx += 256) {
        int lr = idx >> 7;
        int c4 = (idx & 127) << 2;
        int gr = r0 + lr - 1;
        float4 v;
        if (gr >= 0 && gr < HDIM) {
            v = *reinterpret_cast<const float4*>(src + ((size_t)gr << 9) + c4);
            if (isPred) {
                v.x = 1.0f / (1.0f + expf(-v.x));
                v.y = 1.0f / (1.0f + expf(-v.y));
                v.z = 1.0f / (1.0f + expf(-v.z));
                v.w = 1.0f / (1.0f + expf(-v.w));
            }
        } else v = make_float4(0.f, 0.f, 0.f, 0.f);
        s[lr][1 + c4] = v.x; s[lr][2 + c4] = v.y;
        s[lr][3 + c4] = v.z; s[lr][4 + c4] = v.w;
        if (c4 == 0) { s[lr][0] = 0.f; s[lr][513] = 0.f; }
    }
    if (tid < 32) {
        uint32_t a, c;
        image_key(b, a, c);
        if (tid == 0) { skey[0] = a; skey[1] = c; }
    }
    __syncthreads();
    uint32_t k0 = skey[0], k1 = skey[1], tb = s_tb;
    int w = tid >> 5, lane = tid & 31;
    unsigned int myc = 0;
    for (int u = w; u < 128; u += 8) {
        int row8 = u >> 4, seg = u & 15;
        int sc = seg * 32 + lane + 1;
        float L0 = s[row8  ][sc-1], M0 = s[row8  ][sc], R0 = s[row8  ][sc+1];
        float L1 = s[row8+1][sc-1],                     R1 = s[row8+1][sc+1];
        float L2 = s[row8+2][sc-1], M2 = s[row8+2][sc], R2 = s[row8+2][sc+1];
        float gx = (R0 - L0) + 2.0f * (R1 - L1) + (R2 - L2);
        float gy = (L2 + 2.0f * M2 + R2) - (L0 + 2.0f * M0 + R0);
        float z  = gx * gx + gy * gy + 1e-8f;
        bool v = __float_as_uint(z) >= tb;     // == (sqrtf(z) > 0.1f), exact
        int gr = r0 + row8;
        unsigned int word = __ballot_sync(0xffffffffu, v);
        if (lane == 0) {
            g_validbits[b * NWORDS + gr * 16 + seg] = word;
            myc += __popc(word);
        }
        int i = (gr << 9) + seg * 32 + lane;
        uint32_t o0, o1;
        threefry2x32(k0, k1, 0u, (uint32_t)i, o0, o1);
        uint32_t kk = (o0 ^ o1) >> 9;
        bool acc = v && (kk >= KTH);
        unsigned int amask = __ballot_sync(0xffffffffu, acc);
        if (amask) {
            int leader = __ffs(amask) - 1;
            uint32_t base = 0;
            if (lane == leader) base = atomicAdd(&g_candcnt[b], (uint32_t)__popc(amask));
            base = __shfl_sync(0xffffffffu, base, leader);
            if (acc) {
                uint32_t pos = base + __popc(amask & ((1u << lane) - 1u));
                if (pos < CANDCAP) {
                    float uu = __uint_as_float(kk | 0x3F800000u) - 1.0f;
                    uint32_t sb = __float_as_uint(2.0f + uu);
                    g_cand[(size_t)b * CANDCAP + pos] =
                        (((unsigned long long)sb) << 32) | (unsigned long long)(~(uint32_t)i);
                }
            }
        }
    }
    if (lane == 0 && myc) atomicAdd(&blkcnt, myc);
    __syncthreads();
    if (tid == 0 && blkcnt) atomicAdd(&g_nvalid[b], blkcnt);
    // last-finishing block of this image runs selection
    __threadfence();
    __syncthreads();
    if (tid == 0) {
        unsigned int old = atomicAdd(&g_imgdone[b], 1u);
        s_isLast = (old == 63u);
    }
    __syncthreads();
    if (s_isLast) {
        __threadfence();
        uint32_t* hist = reinterpret_cast<uint32_t*>(s_raw);
        unsigned long long* bnd = reinterpret_cast<unsigned long long*>(s_raw + 16384);
        select_image(b, hist, bnd);
    }
}

// ---------------- k_hd_mean: 1024 blocks = 64 img x 2 dir x 8 parts ----------
__global__ void __launch_bounds__(128) k_hd_mean(float* __restrict__ out) {
    __shared__ __align__(16) float rx[NPTSP], ry[NPTSP], rq[NPTSP];
    __shared__ float red[4];
    __shared__ int s_last;
    int blk  = blockIdx.x;
    int b    = blk >> 4;
    int dir  = (blk >> 3) & 1;
    int part = blk & 7;
    int tid  = threadIdx.x;
    int qimg = dir ? (BATCH + b) : b;
    int rimg = dir ? b : (BATCH + b);
    int nq  = g_np[qimg];
    int nr8 = (g_np[rimg] + 7) & ~7;
    if (tid == 0) s_last = 0;
    for (int i = tid; i < nr8; i += 128) {
        rx[i] = g_lx[rimg * NPTSP + i];
        ry[i] = g_ly[rimg * NPTSP + i];
        rq[i] = g_q [rimg * NPTSP + i];
    }
    __syncthreads();
    int ch = (nq + PARTS - 1) / PARTS;
    int i0 = part * ch;
    int i1 = (i0 + ch < nq) ? (i0 + ch) : nq;
    float lmax = 0.0f;
    for (int iq = i0 + tid; iq < i1; iq += 128) {
        float x = g_lx[qimg * NPTSP + iq];
        float y = g_ly[qimg * NPTSP + iq];
        float nx = -2.0f * x, ny = -2.0f * y;
        float xx = fmaf(x, x, y * y);
        float m0 = 3.4e38f, m1 = 3.4e38f;
        for (int j = 0; j < nr8; j += 8) {
            const float4 ta = *reinterpret_cast<const float4*>(&rx[j]);
            const float4 ya = *reinterpret_cast<const float4*>(&ry[j]);
            const float4 qa = *reinterpret_cast<const float4*>(&rq[j]);
            const float4 tb = *reinterpret_cast<const float4*>(&rx[j + 4]);
            const float4 yb = *reinterpret_cast<const float4*>(&ry[j + 4]);
            const float4 qb = *reinterpret_cast<const float4*>(&rq[j + 4]);
            float a0 = fmaf(ta.x, nx, fmaf(ya.x, ny, qa.x));
            float a1 = fmaf(ta.y, nx, fmaf(ya.y, ny, qa.y));
            float a2 = fmaf(ta.z, nx, fmaf(ya.z, ny, qa.z));
            float a3 = fmaf(ta.w, nx, fmaf(ya.w, ny, qa.w));
            float b0 = fmaf(tb.x, nx, fmaf(yb.x, ny, qb.x));
            float b1 = fmaf(tb.y, nx, fmaf(yb.y, ny, qb.y));
            float b2 = fmaf(tb.z, nx, fmaf(yb.z, ny, qb.z));
            float b3 = fmaf(tb.w, nx, fmaf(yb.w, ny, qb.w));
            m0 = fminf(m0, fminf(fminf(a0, a1), fminf(a2, a3)));
            m1 = fminf(m1, fminf(fminf(b0, b1), fminf(b2, b3)));
        }
        float m = fminf(m0, m1);
        lmax = fmaxf(lmax, fmaxf(m + xx, 0.0f));   // d^2, exact
    }
    for (int off = 16; off; off >>= 1)
        lmax = fmaxf(lmax, __shfl_down_sync(0xffffffffu, lmax, off));
    if ((tid & 31) == 0) red[tid >> 5] = lmax;
    __syncthreads();
    if (tid == 0) {
        float vv = fmaxf(fmaxf(red[0], red[1]), fmaxf(red[2], red[3]));
        atomicMax(&g_hdbits[b], __float_as_uint(vv));
        __threadfence();
        unsigned int old = atomicAdd(&g_done, 1u);
        s_last = (old == HDBLOCKS - 1);
    }
    __syncthreads();
    if (s_last && tid == 0) {
        __threadfence();
        float diag = sqrtf((float)(HDIM * HDIM + WDIM * WDIM));
        float ssum = 0.0f;
        for (int i = 0; i < BATCH; i++) {
            float hd = sqrtf(__uint_as_float(g_hdbits[i])) / diag;
            ssum += fminf(fmaxf(hd, 0.0f), 0.1f);
            g_hdbits[i] = 0u;                       // self-clean
        }
        out[0] = ssum / (float)BATCH;
        g_done = 0u;                                // self-clean
    }
}

// ---------------- launch ----------------
extern "C" void kernel_launch(void* const* d_in, const int* in_sizes, int n_in,
                              void* d_out, int out_size) {
    const float* pred   = (const float*)d_in[0];
    const float* target = (const float*)d_in[1];
    float* out = (float*)d_out;

    k_fused<<<NIMG * 64, 256>>>(pred, target);   // Sobel+RNG+accept+selection
    k_hd_mean<<<HDBLOCKS, 128>>>(out);           // Hausdorff + mean
}

// round 10
// speedup vs baseline: 1.3662x; 1.0634x over previous
#include <cuda_runtime.h>
#include <cuda_bf16.h>
#include <stdint.h>

// ---------------- problem constants ----------------
#define BATCH   64
#define HDIM    512
#define WDIM    512
#define NPIX    (HDIM*WDIM)          // 262144
#define NWORDS  (NPIX/32)
#define NIMG    (2*BATCH)            // 128
#define NPTS    1000
#define NPTSP   1008                 // padded stride (mult of 8 + sentinels)
#define CANDCAP 4096
#define PARTS   4
#define HDBLOCKS (BATCH*2*PARTS)     // 512
#define BNDCAP  512
// integer acceptance threshold on (rb>>9): accept iff k >= KTH.
// E[cand] = (2^23 - KTH)/2^23 * nvalid ~ 0.00723 * nvalid ~ 1890.
#define KTH     8327961u

// ---------------- device scratch (zero-init; self-cleaning) ----------------
__device__ uint32_t g_validbits[NIMG*NWORDS];
__device__ uint32_t g_nvalid[NIMG];
__device__ uint32_t g_candcnt[NIMG];
__device__ uint32_t g_imgdone[NIMG];
__device__ unsigned long long g_cand[(size_t)NIMG*CANDCAP];
__device__ float    g_lx[NIMG*NPTSP];
__device__ float    g_ly[NIMG*NPTSP];
__device__ float    g_q [NIMG*NPTSP];
__device__ int      g_np[NIMG];
__device__ unsigned int g_hdbits[BATCH];
__device__ unsigned int g_done;

// ---------------- threefry2x32 (JAX partitionable semantics) ----------------
__device__ __forceinline__ uint32_t rotl32(uint32_t x, int r) {
    return __funnelshift_l(x, x, r);
}
__device__ __forceinline__ void threefry2x32(uint32_t k0, uint32_t k1,
                                             uint32_t x0, uint32_t x1,
                                             uint32_t& o0, uint32_t& o1) {
    uint32_t ks2 = k0 ^ k1 ^ 0x1BD11BDAu;
    x0 += k0; x1 += k1;
#define TF_RND(r) { x0 += x1; x1 = rotl32(x1, r); x1 ^= x0; }
    TF_RND(13) TF_RND(15) TF_RND(26) TF_RND(6)   x0 += k1;  x1 += ks2 + 1u;
    TF_RND(17) TF_RND(29) TF_RND(16) TF_RND(24)  x0 += ks2; x1 += k0  + 2u;
    TF_RND(13) TF_RND(15) TF_RND(26) TF_RND(6)   x0 += k0;  x1 += k1  + 3u;
    TF_RND(17) TF_RND(29) TF_RND(16) TF_RND(24)  x0 += k1;  x1 += ks2 + 4u;
    TF_RND(13) TF_RND(15) TF_RND(26) TF_RND(6)   x0 += ks2; x1 += k0  + 5u;
#undef TF_RND
    o0 = x0; o1 = x1;
}
// pre-added variant: x0_in=0 -> x0=k0; caller passes x1 = k1 + i already added.
__device__ __forceinline__ uint32_t threefry_xor(uint32_t k0, uint32_t k1,
                                                 uint32_t ks2, uint32_t x1) {
    uint32_t x0 = k0;
#define TF_RND(r) { x0 += x1; x1 = rotl32(x1, r); x1 ^= x0; }
    TF_RND(13) TF_RND(15) TF_RND(26) TF_RND(6)   x0 += k1;  x1 += ks2 + 1u;
    TF_RND(17) TF_RND(29) TF_RND(16) TF_RND(24)  x0 += ks2; x1 += k0  + 2u;
    TF_RND(13) TF_RND(15) TF_RND(26) TF_RND(6)   x0 += k0;  x1 += k1  + 3u;
    TF_RND(17) TF_RND(29) TF_RND(16) TF_RND(24)  x0 += k1;  x1 += ks2 + 4u;
    TF_RND(13) TF_RND(15) TF_RND(26) TF_RND(6)   x0 += ks2; x1 += k0  + 5u;
#undef TF_RND
    return x0 ^ x1;
}
__device__ __forceinline__ float bits_to_uniform(uint32_t bits) {
    return __uint_as_float((bits >> 9) | 0x3F800000u) - 1.0f;
}
// partitionable split(key(1),128): key_b = threefry((0,1), (0,b))
__device__ __forceinline__ void image_key(int b, uint32_t& k0, uint32_t& k1) {
    threefry2x32(0u, 1u, 0u, (uint32_t)b, k0, k1);
}

__device__ __forceinline__ void emit_point(int b, unsigned int pos, uint32_t idx) {
    float x = (float)(idx >> 9), y = (float)(idx & 511);
    g_lx[b * NPTSP + pos] = x;
    g_ly[b * NPTSP + pos] = y;
    g_q [b * NPTSP + pos] = x * x + y * y;
}

// ---------------- selection (runs in the last-finishing block of an image) ---
__device__ __noinline__ void select_image(int b, uint32_t* hist,
                                          unsigned long long* bnd) {
    __shared__ uint32_t tsum[256];
    __shared__ uint32_t esuf[256];
    __shared__ unsigned int s_rc, s_emit, s_bcnt, s_C, s_G;
    int tid = threadIdx.x;
    unsigned int cnt = g_candcnt[b]; if (cnt > CANDCAP) cnt = CANDCAP;
    unsigned int nv  = g_nvalid[b];
    unsigned int needed = (nv < (unsigned)NPTS) ? nv : (unsigned)NPTS;
    bool rescued = false;
    if (cnt < needed) {
        // RESCUE: adaptive tau; statistically never taken.
        if (tid == 0) s_rc = 0u;
        __syncthreads();
        uint32_t k0, k1; image_key(b, k0, k1);
        uint32_t tau = 0u;
        if (nv > 2500u)
            tau = __float_as_uint(2.0f + (1.0f - 2048.0f / (float)nv));
        int lane = tid & 31;
        for (int i = tid; i < NPIX; i += 256) {
            uint32_t vw = g_validbits[b * NWORDS + (i >> 5)];
            bool v = (vw >> lane) & 1u;
            uint32_t o0, o1;
            threefry2x32(k0, k1, 0u, (uint32_t)i, o0, o1);
            uint32_t sb = __float_as_uint(2.0f + bits_to_uniform(o0 ^ o1));
            bool acc = v && (sb >= tau);
            unsigned int amask = __ballot_sync(0xffffffffu, acc);
            if (amask) {
                int leader = __ffs(amask) - 1;
                uint32_t base = 0;
                if (lane == leader) base = atomicAdd(&s_rc, (uint32_t)__popc(amask));
                base = __shfl_sync(0xffffffffu, base, leader);
                if (acc) {
                    uint32_t pos = base + __popc(amask & ((1u << lane) - 1u));
                    if (pos < CANDCAP)
                        g_cand[(size_t)b * CANDCAP + pos] =
                            (((unsigned long long)sb) << 32)
                          | (unsigned long long)(~(uint32_t)i);
                }
            }
        }
        __syncthreads();
        cnt = s_rc; if (cnt > CANDCAP) cnt = CANDCAP;
        rescued = true;
    }
    if (needed > cnt) needed = cnt;

    int npts;
    if (cnt == 0u) {
        npts = 1;
        if (tid == 0) {
            g_lx[b * NPTSP] = 256.0f;
            g_ly[b * NPTSP] = 256.0f;
            g_q [b * NPTSP] = 131072.0f;
        }
    } else if (cnt <= needed) {
        npts = (int)cnt;                      // take everything
        for (unsigned int i = tid; i < cnt; i += 256)
            emit_point(b, i, ~(uint32_t)g_cand[(size_t)b * CANDCAP + i]);
    } else {
        npts = (int)needed;
        const uint32_t SB = rescued ? 0x40000000u : 0x403F0000u;
        const int      SH = rescued ? 12 : 4;
        for (int k = tid; k < 4096; k += 256) hist[k] = 0u;
        if (tid == 0) { s_emit = 0u; s_bcnt = 0u; }
        __syncthreads();
        for (unsigned int i = tid; i < cnt; i += 256) {
            uint32_t sb = (uint32_t)(g_cand[(size_t)b * CANDCAP + i] >> 32);
            int bin = (int)((sb - SB) >> SH); if (bin > 4095) bin = 4095;
            atomicAdd(&hist[bin], 1u);
        }
        __syncthreads();
        {   // suffix scan for cutoff bin C, G = count above C
            uint32_t ls = 0;
            int base = tid * 16;
            for (int k = 0; k < 16; k++) ls += hist[base + k];
            tsum[tid] = ls;
        }
        __syncthreads();
        if (tid < 32) {
            uint32_t g = 0;
            for (int k = 0; k < 8; k++) g += tsum[tid * 8 + k];
            uint32_t sfx = g;
            for (int off = 1; off < 32; off <<= 1) {
                uint32_t o = __shfl_down_sync(0xffffffffu, sfx, off);
                if (tid + off < 32) sfx += o;
            }
            uint32_t cum = sfx - g;
            for (int k = 7; k >= 0; k--) {
                esuf[tid * 8 + k] = cum;
                cum += tsum[tid * 8 + k];
            }
        }
        __syncthreads();
        {
            uint32_t sa = esuf[tid];
            if (sa < needed && sa + tsum[tid] >= needed) {
                uint32_t cum = sa;
                for (int bin = tid * 16 + 15; ; bin--) {
                    uint32_t h = hist[bin];
                    if (cum + h >= needed) { s_C = (unsigned)bin; s_G = cum; break; }
                    cum += h;
                }
            }
        }
        __syncthreads();
        unsigned int C = s_C, G = s_G;
        for (unsigned int i = tid; i < cnt; i += 256) {
            unsigned long long key = g_cand[(size_t)b * CANDCAP + i];
            uint32_t sb = (uint32_t)(key >> 32);
            int bin = (int)((sb - SB) >> SH); if (bin > 4095) bin = 4095;
            if (bin > (int)C) {
                unsigned int pos = atomicAdd(&s_emit, 1u);
                emit_point(b, pos, ~(uint32_t)key);
            } else if (bin == (int)C) {
                unsigned int p = atomicAdd(&s_bcnt, 1u);
                if (p < BNDCAP) bnd[p] = key;
            }
        }
        __syncthreads();
        unsigned int bcnt = s_bcnt; if (bcnt > BNDCAP) bcnt = BNDCAP;
        int n2 = 2; while (n2 < (int)bcnt) n2 <<= 1;
        for (int i = (int)bcnt + tid; i < n2; i += 256) bnd[i] = 0ull;
        __syncthreads();
        for (int k = 2; k <= n2; k <<= 1) {           // sort desc by full key
            for (int j = k >> 1; j > 0; j >>= 1) {
                for (int i = tid; i < n2; i += 256) {
                    int ixj = i ^ j;
                    if (ixj > i) {
                        unsigned long long a = bnd[i], bb = bnd[ixj];
                        if ((a < bb) == ((i & k) == 0)) { bnd[i] = bb; bnd[ixj] = a; }
                    }
                }
                __syncthreads();
            }
        }
        unsigned int take = needed - G; if (take > bcnt) take = bcnt;
        for (unsigned int j = tid; j < take; j += 256)
            emit_point(b, G + j, ~(uint32_t)bnd[j]);
    }
    __syncthreads();
    int pad = (npts + 7) & ~7;                       // sentinels
    for (int j = npts + tid; j < pad; j += 256) {
        g_lx[b * NPTSP + j] = 0.0f;
        g_ly[b * NPTSP + j] = 0.0f;
        g_q [b * NPTSP + j] = 3.0e38f;
    }
    if (tid == 0) {
        g_np[b] = npts;
        g_candcnt[b] = 0u;     // self-clean for graph replay
        g_nvalid[b]  = 0u;
        g_imgdone[b] = 0u;
    }
}

// ---------------- k_fused: Sobel(+sigmoid) + threefry + accept + selection ---
__global__ void __launch_bounds__(256) k_fused(const float* __restrict__ pred,
                                               const float* __restrict__ target) {
    __shared__ __align__(16) unsigned char s_raw[20608];
    float (*s)[514] = reinterpret_cast<float(*)[514]>(s_raw);
    __shared__ unsigned int blkcnt;
    __shared__ uint32_t skey[2];
    __shared__ uint32_t s_tb;
    __shared__ int s_isLast;
    int bx  = blockIdx.x;
    int b   = bx >> 6;
    int r0  = (bx & 63) << 3;
    int tid = threadIdx.x;
    if (tid == 0) {
        blkcnt = 0u;
        // exact bits threshold T: z >= T  <=>  sqrtf(z) > 0.1f (sqrt.rn monotone)
        double mid = (double)0.1f + 3.7252902984619140625e-9;  // c + ulp/2, exact
        double T = mid * mid;                                  // exact (50 bits)
        float t1 = (float)T;
        uint32_t tb = __float_as_uint(t1);
        if ((double)t1 < T) tb++;
        s_tb = tb;
    }
    bool isPred = (b < BATCH);
    const float* src = isPred ? (pred + (size_t)b * NPIX)
                              : (target + (size_t)(b - BATCH) * NPIX);
    for (int idx = tid; idx < 1280; idx += 256) {
        int lr = idx >> 7;
        int c4 = (idx & 127) << 2;
        int gr = r0 + lr - 1;
        float4 v;
        if (gr >= 0 && gr < HDIM) {
            v = *reinterpret_cast<const float4*>(src + ((size_t)gr << 9) + c4);
            if (isPred) {
                v.x = 1.0f / (1.0f + expf(-v.x));
                v.y = 1.0f / (1.0f + expf(-v.y));
                v.z = 1.0f / (1.0f + expf(-v.z));
                v.w = 1.0f / (1.0f + expf(-v.w));
            }
        } else v = make_float4(0.f, 0.f, 0.f, 0.f);
        s[lr][1 + c4] = v.x; s[lr][2 + c4] = v.y;
        s[lr][3 + c4] = v.z; s[lr][4 + c4] = v.w;
        if (c4 == 0) { s[lr][0] = 0.f; s[lr][513] = 0.f; }
    }
    if (tid < 32) {
        uint32_t a, c;
        image_key(b, a, c);
        if (tid == 0) { skey[0] = a; skey[1] = c; }
    }
    __syncthreads();
    const uint32_t k0 = skey[0], k1 = skey[1], tb = s_tb;
    const uint32_t ks2 = k0 ^ k1 ^ 0x1BD11BDAu;
    const int w = tid >> 5, lane = tid & 31;
    // affine bases: u = w + 8*it -> row8 = it>>1, seg = w + 8*(it&1)
    const int sc0   = w * 32 + lane + 1;          // + 256*(it&1)
    const uint32_t ibase = (uint32_t)((r0 << 9) + w * 32 + lane);  // + 256*it
    const uint32_t k1i   = k1 + ibase;
    const int vb0   = b * NWORDS + r0 * 16 + w;   // + (it>>1)*16 + 8*(it&1)
    unsigned int myc = 0;
#pragma unroll
    for (int it = 0; it < 16; it++) {
        const int row8 = it >> 1;
        const int sc = sc0 + (it & 1) * 256;
        float L0 = s[row8  ][sc-1], M0 = s[row8  ][sc], R0 = s[row8  ][sc+1];
        float L1 = s[row8+1][sc-1],                     R1 = s[row8+1][sc+1];
        float L2 = s[row8+2][sc-1], M2 = s[row8+2][sc], R2 = s[row8+2][sc+1];
        float gx = (R0 - L0) + 2.0f * (R1 - L1) + (R2 - L2);
        float gy = (L2 + 2.0f * M2 + R2) - (L0 + 2.0f * M0 + R0);
        float z  = gx * gx + gy * gy + 1e-8f;
        bool v = __float_as_uint(z) >= tb;       // == (sqrtf(z) > 0.1f), exact
        unsigned int word = __ballot_sync(0xffffffffu, v);
        if (lane == 0) {
            g_validbits[vb0 + row8 * 16 + (it & 1) * 8] = word;
            myc += __popc(word);
        }
        uint32_t kk = threefry_xor(k0, k1, ks2, k1i + 256u * (uint32_t)it) >> 9;
        unsigned int amask = word & __ballot_sync(0xffffffffu, kk >= KTH);
        if (amask) {
            bool acc = (amask >> lane) & 1u;
            int leader = __ffs(amask) - 1;
            uint32_t base = 0;
            if (lane == leader) base = atomicAdd(&g_candcnt[b], (uint32_t)__popc(amask));
            base = __shfl_sync(0xffffffffu, base, leader);
            if (acc) {
                uint32_t pos = base + __popc(amask & ((1u << lane) - 1u));
                if (pos < CANDCAP) {
                    float uu = __uint_as_float(kk | 0x3F800000u) - 1.0f;
                    uint32_t sb = __float_as_uint(2.0f + uu);
                    uint32_t i = ibase + 256u * (uint32_t)it;
                    g_cand[(size_t)b * CANDCAP + pos] =
                        (((unsigned long long)sb) << 32) | (unsigned long long)(~i);
                }
            }
        }
    }
    if (lane == 0 && myc) atomicAdd(&blkcnt, myc);
    __syncthreads();
    if (tid == 0 && blkcnt) atomicAdd(&g_nvalid[b], blkcnt);
    // last-finishing block of this image runs selection
    __threadfence();
    __syncthreads();
    if (tid == 0) {
        unsigned int old = atomicAdd(&g_imgdone[b], 1u);
        s_isLast = (old == 63u);
    }
    __syncthreads();
    if (s_isLast) {
        __threadfence();
        uint32_t* hist = reinterpret_cast<uint32_t*>(s_raw);
        unsigned long long* bnd = reinterpret_cast<unsigned long long*>(s_raw + 16384);
        select_image(b, hist, bnd);
    }
}

// ---------------- k_hd_mean: 512 blocks = 64 img x 2 dir x 4 parts -----------
// 2 register-resident queries per thread: halves LDS traffic, doubles FMA ILP.
__global__ void __launch_bounds__(128) k_hd_mean(float* __restrict__ out) {
    __shared__ __align__(16) float rx[NPTSP], ry[NPTSP], rq[NPTSP];
    __shared__ float red[4];
    __shared__ int s_last;
    int blk  = blockIdx.x;
    int b    = blk >> 3;
    int dir  = (blk >> 2) & 1;
    int part = blk & 3;
    int tid  = threadIdx.x;
    int qimg = dir ? (BATCH + b) : b;
    int rimg = dir ? b : (BATCH + b);
    int nq  = g_np[qimg];
    int nr8 = (g_np[rimg] + 7) & ~7;
    if (tid == 0) s_last = 0;
    for (int i = tid; i < nr8; i += 128) {
        rx[i] = g_lx[rimg * NPTSP + i];
        ry[i] = g_ly[rimg * NPTSP + i];
        rq[i] = g_q [rimg * NPTSP + i];
    }
    __syncthreads();
    int ch = (nq + PARTS - 1) / PARTS;       // <= 250
    int i0 = part * ch;
    int i1 = (i0 + ch < nq) ? (i0 + ch) : nq;
    int iqA = i0 + tid, iqB = i0 + tid + 128;
    bool actA = iqA < i1, actB = iqB < i1;
    int rdA = actA ? iqA : 0, rdB = actB ? iqB : 0;
    float xA = g_lx[qimg * NPTSP + rdA], yA = g_ly[qimg * NPTSP + rdA];
    float xB = g_lx[qimg * NPTSP + rdB], yB = g_ly[qimg * NPTSP + rdB];
    float nxA = -2.0f * xA, nyA = -2.0f * yA;
    float nxB = -2.0f * xB, nyB = -2.0f * yB;
    float xxA = fmaf(xA, xA, yA * yA);
    float xxB = fmaf(xB, xB, yB * yB);
    float mA0 = 3.4e38f, mA1 = 3.4e38f, mB0 = 3.4e38f, mB1 = 3.4e38f;
    for (int j = 0; j < nr8; j += 8) {
        const float4 ta = *reinterpret_cast<const float4*>(&rx[j]);
        const float4 ya = *reinterpret_cast<const float4*>(&ry[j]);
        const float4 qa = *reinterpret_cast<const float4*>(&rq[j]);
        const float4 tc = *reinterpret_cast<const float4*>(&rx[j + 4]);
        const float4 yc = *reinterpret_cast<const float4*>(&ry[j + 4]);
        const float4 qc = *reinterpret_cast<const float4*>(&rq[j + 4]);
        float a0 = fmaf(ta.x, nxA, fmaf(ya.x, nyA, qa.x));
        float a1 = fmaf(ta.y, nxA, fmaf(ya.y, nyA, qa.y));
        float a2 = fmaf(ta.z, nxA, fmaf(ya.z, nyA, qa.z));
        float a3 = fmaf(ta.w, nxA, fmaf(ya.w, nyA, qa.w));
        float a4 = fmaf(tc.x, nxA, fmaf(yc.x, nyA, qc.x));
        float a5 = fmaf(tc.y, nxA, fmaf(yc.y, nyA, qc.y));
        float a6 = fmaf(tc.z, nxA, fmaf(yc.z, nyA, qc.z));
        float a7 = fmaf(tc.w, nxA, fmaf(yc.w, nyA, qc.w));
        float b0 = fmaf(ta.x, nxB, fmaf(ya.x, nyB, qa.x));
        float b1 = fmaf(ta.y, nxB, fmaf(ya.y, nyB, qa.y));
        float b2 = fmaf(ta.z, nxB, fmaf(ya.z, nyB, qa.z));
        float b3 = fmaf(ta.w, nxB, fmaf(ya.w, nyB, qa.w));
        float b4 = fmaf(tc.x, nxB, fmaf(yc.x, nyB, qc.x));
        float b5 = fmaf(tc.y, nxB, fmaf(yc.y, nyB, qc.y));
        float b6 = fmaf(tc.z, nxB, fmaf(yc.z, nyB, qc.z));
        float b7 = fmaf(tc.w, nxB, fmaf(yc.w, nyB, qc.w));
        mA0 = fminf(mA0, fminf(fminf(a0, a1), fminf(a2, a3)));
        mA1 = fminf(mA1, fminf(fminf(a4, a5), fminf(a6, a7)));
        mB0 = fminf(mB0, fminf(fminf(b0, b1), fminf(b2, b3)));
        mB1 = fminf(mB1, fminf(fminf(b4, b5), fminf(b6, b7)));
    }
    float lmax = 0.0f;
    if (actA) lmax = fmaxf(lmax, fmaxf(fminf(mA0, mA1) + xxA, 0.0f));
    if (actB) lmax = fmaxf(lmax, fmaxf(fminf(mB0, mB1) + xxB, 0.0f));
    for (int off = 16; off; off >>= 1)
        lmax = fmaxf(lmax, __shfl_down_sync(0xffffffffu, lmax, off));
    if ((tid & 31) == 0) red[tid >> 5] = lmax;
    __syncthreads();
    if (tid == 0) {
        float vv = fmaxf(fmaxf(red[0], red[1]), fmaxf(red[2], red[3]));
        atomicMax(&g_hdbits[b], __float_as_uint(vv));
        __threadfence();
        unsigned int old = atomicAdd(&g_done, 1u);
        s_last = (old == HDBLOCKS - 1);
    }
    __syncthreads();
    if (s_last && tid == 0) {
        __threadfence();
        float diag = sqrtf((float)(HDIM * HDIM + WDIM * WDIM));
        float ssum = 0.0f;
        for (int i = 0; i < BATCH; i++) {
            float hd = sqrtf(__uint_as_float(g_hdbits[i])) / diag;
            ssum += fminf(fmaxf(hd, 0.0f), 0.1f);
            g_hdbits[i] = 0u;                       // self-clean
        }
        out[0] = ssum / (float)BATCH;
        g_done = 0u;                                // self-clean
    }
}

// ---------------- launch ----------------
extern "C" void kernel_launch(void* const* d_in, const int* in_sizes, int n_in,
                              void* d_out, int out_size) {
    const float* pred   = (const float*)d_in[0];
    const float* target = (const float*)d_in[1];
    float* out = (float*)d_out;

    k_fused<<<NIMG * 64, 256>>>(pred, target);   // Sobel+RNG+accept+selection
    k_hd_mean<<<HDBLOCKS, 128>>>(out);           // Hausdorff + mean
}

// round 11
// speedup vs baseline: 1.3742x; 1.0058x over previous
#include <cuda_runtime.h>
#include <cuda_bf16.h>
#include <stdint.h>

// ---------------- problem constants ----------------
#define BATCH   64
#define HDIM    512
#define WDIM    512
#define NPIX    (HDIM*WDIM)          // 262144
#define NWORDS  (NPIX/32)
#define NIMG    (2*BATCH)            // 128
#define NPTS    1000
#define NPTSP   1008                 // padded stride (mult of 8 + sentinels)
#define CANDCAP 4096
#define PARTS   4
#define HDBLOCKS (BATCH*2*PARTS)     // 512
#define BNDCAP  512
// integer acceptance threshold: accept iff rnd >= KTH9 (== (rnd>>9) >= KTH).
// E[cand] ~ 0.00723 * nvalid ~ 1890.
#define KTH     8327961u
#define KTH9    4263916032u          // KTH << 9

// ---------------- device scratch (zero-init; self-cleaning) ----------------
__device__ uint32_t g_validbits[NIMG*NWORDS];
__device__ uint32_t g_nvalid[NIMG];
__device__ uint32_t g_candcnt[NIMG];
__device__ uint32_t g_imgdone[NIMG];
__device__ unsigned long long g_cand[(size_t)NIMG*CANDCAP];
__device__ float    g_lx[NIMG*NPTSP];
__device__ float    g_ly[NIMG*NPTSP];
__device__ float    g_q [NIMG*NPTSP];
__device__ int      g_np[NIMG];
__device__ unsigned int g_hdbits[BATCH];
__device__ unsigned int g_done;

// ---------------- threefry2x32 (JAX partitionable semantics) ----------------
__device__ __forceinline__ uint32_t rotl32(uint32_t x, int r) {
    return __funnelshift_l(x, x, r);
}
__device__ __forceinline__ void threefry2x32(uint32_t k0, uint32_t k1,
                                             uint32_t x0, uint32_t x1,
                                             uint32_t& o0, uint32_t& o1) {
    uint32_t ks2 = k0 ^ k1 ^ 0x1BD11BDAu;
    x0 += k0; x1 += k1;
#define TF_RND(r) { x0 += x1; x1 = rotl32(x1, r); x1 ^= x0; }
    TF_RND(13) TF_RND(15) TF_RND(26) TF_RND(6)   x0 += k1;  x1 += ks2 + 1u;
    TF_RND(17) TF_RND(29) TF_RND(16) TF_RND(24)  x0 += ks2; x1 += k0  + 2u;
    TF_RND(13) TF_RND(15) TF_RND(26) TF_RND(6)   x0 += k0;  x1 += k1  + 3u;
    TF_RND(17) TF_RND(29) TF_RND(16) TF_RND(24)  x0 += k1;  x1 += ks2 + 4u;
    TF_RND(13) TF_RND(15) TF_RND(26) TF_RND(6)   x0 += ks2; x1 += k0  + 5u;
#undef TF_RND
    o0 = x0; o1 = x1;
}
// pre-added variant: x1 = k1 + counter already added by caller.
__device__ __forceinline__ uint32_t threefry_xor(uint32_t k0, uint32_t k1,
                                                 uint32_t ks2, uint32_t x1) {
    uint32_t x0 = k0;
#define TF_RND(r) { x0 += x1; x1 = rotl32(x1, r); x1 ^= x0; }
    TF_RND(13) TF_RND(15) TF_RND(26) TF_RND(6)   x0 += k1;  x1 += ks2 + 1u;
    TF_RND(17) TF_RND(29) TF_RND(16) TF_RND(24)  x0 += ks2; x1 += k0  + 2u;
    TF_RND(13) TF_RND(15) TF_RND(26) TF_RND(6)   x0 += k0;  x1 += k1  + 3u;
    TF_RND(17) TF_RND(29) TF_RND(16) TF_RND(24)  x0 += k1;  x1 += ks2 + 4u;
    TF_RND(13) TF_RND(15) TF_RND(26) TF_RND(6)   x0 += ks2; x1 += k0  + 5u;
#undef TF_RND
    return x0 ^ x1;
}
__device__ __forceinline__ float bits_to_uniform(uint32_t bits) {
    return __uint_as_float((bits >> 9) | 0x3F800000u) - 1.0f;
}
// partitionable split(key(1),128): key_b = threefry((0,1), (0,b))
__device__ __forceinline__ void image_key(int b, uint32_t& k0, uint32_t& k1) {
    threefry2x32(0u, 1u, 0u, (uint32_t)b, k0, k1);
}

__device__ __forceinline__ void emit_point(int b, unsigned int pos, uint32_t idx) {
    float x = (float)(idx >> 9), y = (float)(idx & 511);
    g_lx[b * NPTSP + pos] = x;
    g_ly[b * NPTSP + pos] = y;
    g_q [b * NPTSP + pos] = x * x + y * y;
}

// ---------------- selection (runs in the last-finishing block of an image) ---
__device__ __noinline__ void select_image(int b, uint32_t* hist,
                                          unsigned long long* bnd) {
    __shared__ uint32_t tsum[256];
    __shared__ uint32_t esuf[256];
    __shared__ unsigned int s_rc, s_emit, s_bcnt, s_C, s_G;
    int tid = threadIdx.x;
    unsigned int cnt = g_candcnt[b]; if (cnt > CANDCAP) cnt = CANDCAP;
    unsigned int nv  = g_nvalid[b];
    unsigned int needed = (nv < (unsigned)NPTS) ? nv : (unsigned)NPTS;
    bool rescued = false;
    if (cnt < needed) {
        // RESCUE: adaptive tau; statistically never taken.
        if (tid == 0) s_rc = 0u;
        __syncthreads();
        uint32_t k0, k1; image_key(b, k0, k1);
        uint32_t tau = 0u;
        if (nv > 2500u)
            tau = __float_as_uint(2.0f + (1.0f - 2048.0f / (float)nv));
        int lane = tid & 31;
        for (int i = tid; i < NPIX; i += 256) {
            uint32_t vw = g_validbits[b * NWORDS + (i >> 5)];
            bool v = (vw >> lane) & 1u;
            uint32_t o0, o1;
            threefry2x32(k0, k1, 0u, (uint32_t)i, o0, o1);
            uint32_t sb = __float_as_uint(2.0f + bits_to_uniform(o0 ^ o1));
            bool acc = v && (sb >= tau);
            unsigned int amask = __ballot_sync(0xffffffffu, acc);
            if (amask) {
                int leader = __ffs(amask) - 1;
                uint32_t base = 0;
                if (lane == leader) base = atomicAdd(&s_rc, (uint32_t)__popc(amask));
                base = __shfl_sync(0xffffffffu, base, leader);
                if (acc) {
                    uint32_t pos = base + __popc(amask & ((1u << lane) - 1u));
                    if (pos < CANDCAP)
                        g_cand[(size_t)b * CANDCAP + pos] =
                            (((unsigned long long)sb) << 32)
                          | (unsigned long long)(~(uint32_t)i);
                }
            }
        }
        __syncthreads();
        cnt = s_rc; if (cnt > CANDCAP) cnt = CANDCAP;
        rescued = true;
    }
    if (needed > cnt) needed = cnt;

    int npts;
    if (cnt == 0u) {
        npts = 1;
        if (tid == 0) {
            g_lx[b * NPTSP] = 256.0f;
            g_ly[b * NPTSP] = 256.0f;
            g_q [b * NPTSP] = 131072.0f;
        }
    } else if (cnt <= needed) {
        npts = (int)cnt;                      // take everything
        for (unsigned int i = tid; i < cnt; i += 256)
            emit_point(b, i, ~(uint32_t)g_cand[(size_t)b * CANDCAP + i]);
    } else {
        npts = (int)needed;
        const uint32_t SB = rescued ? 0x40000000u : 0x403F0000u;
        const int      SH = rescued ? 12 : 4;
        for (int k = tid; k < 4096; k += 256) hist[k] = 0u;
        if (tid == 0) { s_emit = 0u; s_bcnt = 0u; }
        __syncthreads();
        for (unsigned int i = tid; i < cnt; i += 256) {
            uint32_t sb = (uint32_t)(g_cand[(size_t)b * CANDCAP + i] >> 32);
            int bin = (int)((sb - SB) >> SH); if (bin > 4095) bin = 4095;
            atomicAdd(&hist[bin], 1u);
        }
        __syncthreads();
        {   // suffix scan for cutoff bin C, G = count above C
            uint32_t ls = 0;
            int base = tid * 16;
            for (int k = 0; k < 16; k++) ls += hist[base + k];
            tsum[tid] = ls;
        }
        __syncthreads();
        if (tid < 32) {
            uint32_t g = 0;
            for (int k = 0; k < 8; k++) g += tsum[tid * 8 + k];
            uint32_t sfx = g;
            for (int off = 1; off < 32; off <<= 1) {
                uint32_t o = __shfl_down_sync(0xffffffffu, sfx, off);
                if (tid + off < 32) sfx += o;
            }
            uint32_t cum = sfx - g;
            for (int k = 7; k >= 0; k--) {
                esuf[tid * 8 + k] = cum;
                cum += tsum[tid * 8 + k];
            }
        }
        __syncthreads();
        {
            uint32_t sa = esuf[tid];
            if (sa < needed && sa + tsum[tid] >= needed) {
                uint32_t cum = sa;
                for (int bin = tid * 16 + 15; ; bin--) {
                    uint32_t h = hist[bin];
                    if (cum + h >= needed) { s_C = (unsigned)bin; s_G = cum; break; }
                    cum += h;
                }
            }
        }
        __syncthreads();
        unsigned int C = s_C, G = s_G;
        for (unsigned int i = tid; i < cnt; i += 256) {
            unsigned long long key = g_cand[(size_t)b * CANDCAP + i];
            uint32_t sb = (uint32_t)(key >> 32);
            int bin = (int)((sb - SB) >> SH); if (bin > 4095) bin = 4095;
            if (bin > (int)C) {
                unsigned int pos = atomicAdd(&s_emit, 1u);
                emit_point(b, pos, ~(uint32_t)key);
            } else if (bin == (int)C) {
                unsigned int p = atomicAdd(&s_bcnt, 1u);
                if (p < BNDCAP) bnd[p] = key;
            }
        }
        __syncthreads();
        unsigned int bcnt = s_bcnt; if (bcnt > BNDCAP) bcnt = BNDCAP;
        int n2 = 2; while (n2 < (int)bcnt) n2 <<= 1;
        for (int i = (int)bcnt + tid; i < n2; i += 256) bnd[i] = 0ull;
        __syncthreads();
        for (int k = 2; k <= n2; k <<= 1) {           // sort desc by full key
            for (int j = k >> 1; j > 0; j >>= 1) {
                for (int i = tid; i < n2; i += 256) {
                    int ixj = i ^ j;
                    if (ixj > i) {
                        unsigned long long a = bnd[i], bb = bnd[ixj];
                        if ((a < bb) == ((i & k) == 0)) { bnd[i] = bb; bnd[ixj] = a; }
                    }
                }
                __syncthreads();
            }
        }
        unsigned int take = needed - G; if (take > bcnt) take = bcnt;
        for (unsigned int j = tid; j < take; j += 256)
            emit_point(b, G + j, ~(uint32_t)bnd[j]);
    }
    __syncthreads();
    int pad = (npts + 7) & ~7;                       // sentinels
    for (int j = npts + tid; j < pad; j += 256) {
        g_lx[b * NPTSP + j] = 0.0f;
        g_ly[b * NPTSP + j] = 0.0f;
        g_q [b * NPTSP + j] = 3.0e38f;
    }
    if (tid == 0) {
        g_np[b] = npts;
        g_candcnt[b] = 0u;     // self-clean for graph replay
        g_nvalid[b]  = 0u;
        g_imgdone[b] = 0u;
    }
}

// ---------------- k_fused: Sobel(+sigmoid) + threefry + accept + selection ---
__global__ void __launch_bounds__(256) k_fused(const float* __restrict__ pred,
                                               const float* __restrict__ target) {
    __shared__ __align__(16) unsigned char s_raw[20608];
    float (*s)[514] = reinterpret_cast<float(*)[514]>(s_raw);
    __shared__ unsigned int blkcnt;
    __shared__ uint32_t skey[2];
    __shared__ uint32_t s_tb;
    __shared__ int s_isLast;
    int bx  = blockIdx.x;
    int b   = bx >> 6;
    int r0  = (bx & 63) << 3;
    int tid = threadIdx.x;
    if (tid == 0) {
        blkcnt = 0u;
        // exact bits threshold T: z >= T  <=>  sqrtf(z) > 0.1f (sqrt.rn monotone)
        double mid = (double)0.1f + 3.7252902984619140625e-9;  // c + ulp/2, exact
        double T = mid * mid;                                  // exact (50 bits)
        float t1 = (float)T;
        uint32_t tb = __float_as_uint(t1);
        if ((double)t1 < T) tb++;
        s_tb = tb;
    }
    bool isPred = (b < BATCH);
    const float* src = isPred ? (pred + (size_t)b * NPIX)
                              : (target + (size_t)(b - BATCH) * NPIX);
    for (int idx = tid; idx < 1280; idx += 256) {
        int lr = idx >> 7;
        int c4 = (idx & 127) << 2;
        int gr = r0 + lr - 1;
        float4 v;
        if (gr >= 0 && gr < HDIM) {
            v = *reinterpret_cast<const float4*>(src + ((size_t)gr << 9) + c4);
            if (isPred) {
                // fast sigmoid (MUFU.EX2 + MUFU.RCP); threshold-bit accuracy
                // analysis: flips only pixels within ~1e-6 of |grad|=0.1.
                v.x = __fdividef(1.0f, 1.0f + __expf(-v.x));
                v.y = __fdividef(1.0f, 1.0f + __expf(-v.y));
                v.z = __fdividef(1.0f, 1.0f + __expf(-v.z));
                v.w = __fdividef(1.0f, 1.0f + __expf(-v.w));
            }
        } else v = make_float4(0.f, 0.f, 0.f, 0.f);
        s[lr][1 + c4] = v.x; s[lr][2 + c4] = v.y;
        s[lr][3 + c4] = v.z; s[lr][4 + c4] = v.w;
        if (c4 == 0) { s[lr][0] = 0.f; s[lr][513] = 0.f; }
    }
    if (tid < 32) {
        uint32_t a, c;
        image_key(b, a, c);
        if (tid == 0) { skey[0] = a; skey[1] = c; }
    }
    __syncthreads();
    const uint32_t k0 = skey[0], k1 = skey[1], tb = s_tb;
    const uint32_t ks2 = k0 ^ k1 ^ 0x1BD11BDAu;
    const int w = tid >> 5, lane = tid & 31;
    const int sc0   = w * 32 + lane + 1;          // + 256*(it&1)
    const uint32_t ibase = (uint32_t)((r0 << 9) + w * 32 + lane);  // + 256*it
    const uint32_t k1i   = k1 + ibase;
    const int vb0   = b * NWORDS + r0 * 16 + w;   // + (it>>1)*16 + 8*(it&1)
    unsigned int myc = 0;
#pragma unroll
    for (int it = 0; it < 16; it++) {
        const int row8 = it >> 1;
        const int sc = sc0 + (it & 1) * 256;
        float L0 = s[row8  ][sc-1], M0 = s[row8  ][sc], R0 = s[row8  ][sc+1];
        float L1 = s[row8+1][sc-1],                     R1 = s[row8+1][sc+1];
        float L2 = s[row8+2][sc-1], M2 = s[row8+2][sc], R2 = s[row8+2][sc+1];
        float gx = (R0 - L0) + 2.0f * (R1 - L1) + (R2 - L2);
        float gy = (L2 + 2.0f * M2 + R2) - (L0 + 2.0f * M0 + R0);
        float z  = gx * gx + gy * gy + 1e-8f;
        bool v = __float_as_uint(z) >= tb;       // == (sqrtf(z) > 0.1f), exact
        unsigned int word = __ballot_sync(0xffffffffu, v);
        if (lane == 0) {
            g_validbits[vb0 + row8 * 16 + (it & 1) * 8] = word;
            myc += __popc(word);
        }
        uint32_t rnd = threefry_xor(k0, k1, ks2, k1i + 256u * (uint32_t)it);
        unsigned int amask = word & __ballot_sync(0xffffffffu, rnd >= KTH9);
        if (amask) {
            bool acc = (amask >> lane) & 1u;
            int leader = __ffs(amask) - 1;
            uint32_t base = 0;
            if (lane == leader) base = atomicAdd(&g_candcnt[b], (uint32_t)__popc(amask));
            base = __shfl_sync(0xffffffffu, base, leader);
            if (acc) {
                uint32_t pos = base + __popc(amask & ((1u << lane) - 1u));
                if (pos < CANDCAP) {
                    uint32_t kk = rnd >> 9;
                    float uu = __uint_as_float(kk | 0x3F800000u) - 1.0f;
                    uint32_t sb = __float_as_uint(2.0f + uu);
                    uint32_t i = ibase + 256u * (uint32_t)it;
                    g_cand[(size_t)b * CANDCAP + pos] =
                        (((unsigned long long)sb) << 32) | (unsigned long long)(~i);
                }
            }
        }
    }
    if (lane == 0 && myc) atomicAdd(&blkcnt, myc);
    __syncthreads();
    if (tid == 0 && blkcnt) atomicAdd(&g_nvalid[b], blkcnt);
    // last-finishing block of this image runs selection
    __threadfence();
    __syncthreads();
    if (tid == 0) {
        unsigned int old = atomicAdd(&g_imgdone[b], 1u);
        s_isLast = (old == 63u);
    }
    __syncthreads();
    if (s_isLast) {
        __threadfence();
        uint32_t* hist = reinterpret_cast<uint32_t*>(s_raw);
        unsigned long long* bnd = reinterpret_cast<unsigned long long*>(s_raw + 16384);
        select_image(b, hist, bnd);
    }
}

// ---------------- k_hd_mean: 512 blocks = 64 img x 2 dir x 4 parts -----------
// 4 register-resident queries per thread, 64 threads: quarter LDS per pair,
// 8 independent FMA chains per thread hide FMNMX/LDS latency.
__global__ void __launch_bounds__(64) k_hd_mean(float* __restrict__ out) {
    __shared__ __align__(16) float rx[NPTSP], ry[NPTSP], rq[NPTSP];
    __shared__ float red[2];
    __shared__ int s_last;
    int blk  = blockIdx.x;
    int b    = blk >> 3;
    int dir  = (blk >> 2) & 1;
    int part = blk & 3;
    int tid  = threadIdx.x;
    int qimg = dir ? (BATCH + b) : b;
    int rimg = dir ? b : (BATCH + b);
    int nq  = g_np[qimg];
    int nr8 = (g_np[rimg] + 7) & ~7;
    if (tid == 0) s_last = 0;
    for (int i = tid; i < nr8; i += 64) {
        rx[i] = g_lx[rimg * NPTSP + i];
        ry[i] = g_ly[rimg * NPTSP + i];
        rq[i] = g_q [rimg * NPTSP + i];
    }
    __syncthreads();
    int ch = (nq + PARTS - 1) / PARTS;       // <= 250
    int i0 = part * ch;
    int i1 = (i0 + ch < nq) ? (i0 + ch) : nq;
    bool act[4]; float NX[4], NY[4], XX[4], m0[4], m1[4];
#pragma unroll
    for (int k = 0; k < 4; k++) {
        int iq = i0 + tid + 64 * k;
        act[k] = iq < i1;
        int rd = act[k] ? iq : 0;
        float x = g_lx[qimg * NPTSP + rd];
        float y = g_ly[qimg * NPTSP + rd];
        NX[k] = -2.0f * x; NY[k] = -2.0f * y;
        XX[k] = fmaf(x, x, y * y);
        m0[k] = 3.4e38f; m1[k] = 3.4e38f;
    }
#pragma unroll 2
    for (int j = 0; j < nr8; j += 8) {
        const float4 ta = *reinterpret_cast<const float4*>(&rx[j]);
        const float4 ya = *reinterpret_cast<const float4*>(&ry[j]);
        const float4 qa = *reinterpret_cast<const float4*>(&rq[j]);
        const float4 tc = *reinterpret_cast<const float4*>(&rx[j + 4]);
        const float4 yc = *reinterpret_cast<const float4*>(&ry[j + 4]);
        const float4 qc = *reinterpret_cast<const float4*>(&rq[j + 4]);
#pragma unroll
        for (int k = 0; k < 4; k++) {
            float a0 = fmaf(ta.x, NX[k], fmaf(ya.x, NY[k], qa.x));
            float a1 = fmaf(ta.y, NX[k], fmaf(ya.y, NY[k], qa.y));
            float a2 = fmaf(ta.z, NX[k], fmaf(ya.z, NY[k], qa.z));
            float a3 = fmaf(ta.w, NX[k], fmaf(ya.w, NY[k], qa.w));
            float a4 = fmaf(tc.x, NX[k], fmaf(yc.x, NY[k], qc.x));
            float a5 = fmaf(tc.y, NX[k], fmaf(yc.y, NY[k], qc.y));
            float a6 = fmaf(tc.z, NX[k], fmaf(yc.z, NY[k], qc.z));
            float a7 = fmaf(tc.w, NX[k], fmaf(yc.w, NY[k], qc.w));
            m0[k] = fminf(m0[k], fminf(fminf(a0, a1), fminf(a2, a3)));
            m1[k] = fminf(m1[k], fminf(fminf(a4, a5), fminf(a6, a7)));
        }
    }
    float lmax = 0.0f;
#pragma unroll
    for (int k = 0; k < 4; k++)
        if (act[k]) lmax = fmaxf(lmax, fmaxf(fminf(m0[k], m1[k]) + XX[k], 0.0f));
    for (int off = 16; off; off >>= 1)
        lmax = fmaxf(lmax, __shfl_down_sync(0xffffffffu, lmax, off));
    if ((tid & 31) == 0) red[tid >> 5] = lmax;
    __syncthreads();
    if (tid == 0) {
        float vv = fmaxf(red[0], red[1]);
        atomicMax(&g_hdbits[b], __float_as_uint(vv));
        __threadfence();
        unsigned int old = atomicAdd(&g_done, 1u);
        s_last = (old == HDBLOCKS - 1);
    }
    __syncthreads();
    if (s_last && tid == 0) {
        __threadfence();
        float diag = sqrtf((float)(HDIM * HDIM + WDIM * WDIM));
        float ssum = 0.0f;
        for (int i = 0; i < BATCH; i++) {
            float hd = sqrtf(__uint_as_float(g_hdbits[i])) / diag;
            ssum += fminf(fmaxf(hd, 0.0f), 0.1f);
            g_hdbits[i] = 0u;                       // self-clean
        }
        out[0] = ssum / (float)BATCH;
        g_done = 0u;                                // self-clean
    }
}

// ---------------- launch ----------------
extern "C" void kernel_launch(void* const* d_in, const int* in_sizes, int n_in,
                              void* d_out, int out_size) {
    const float* pred   = (const float*)d_in[0];
    const float* target = (const float*)d_in[1];
    float* out = (float*)d_out;

    k_fused<<<NIMG * 64, 256>>>(pred, target);   // Sobel+RNG+accept+selection
    k_hd_mean<<<HDBLOCKS, 64>>>(out);            // Hausdorff + mean
}

// round 13
// speedup vs baseline: 1.4146x; 1.0294x over previous
#include <cuda_runtime.h>
#include <cuda_bf16.h>
#include <stdint.h>

// ---------------- problem constants ----------------
#define BATCH   64
#define HDIM    512
#define WDIM    512
#define NPIX    (HDIM*WDIM)          // 262144
#define NWORDS  (NPIX/32)
#define NIMG    (2*BATCH)            // 128
#define NPTS    1000
#define NPTSP   1008                 // padded stride (mult of 8 + sentinels)
#define CANDCAP 4096
#define PARTS   4
#define HDBLOCKS (BATCH*2*PARTS)     // 512
#define BNDCAP  512
// integer acceptance threshold: accept iff rnd >= KTH9 (== (rnd>>9) >= KTH).
// E[cand] ~ 0.00723 * nvalid ~ 1890.
#define KTH     8327961u
#define KTH9    4263916032u          // KTH << 9

// packed f32x2 FMA (Blackwell): halves fma-pipe instruction count.
#define FMA2(out, a, b, c) \
    asm("fma.rn.f32x2 %0, %1, %2, %3;" : "=l"(out) : "l"(a), "l"(b), "l"(c))

__device__ __forceinline__ unsigned long long pack2(float x) {
    uint32_t b = __float_as_uint(x);
    return ((unsigned long long)b << 32) | (unsigned long long)b;
}
__device__ __forceinline__ float lo2(unsigned long long v) {
    return __uint_as_float((uint32_t)v);
}
__device__ __forceinline__ float hi2(unsigned long long v) {
    return __uint_as_float((uint32_t)(v >> 32));
}

// ---------------- device scratch (zero-init; self-cleaning) ----------------
__device__ uint32_t g_validbits[NIMG*NWORDS];
__device__ uint32_t g_nvalid[NIMG];
__device__ uint32_t g_candcnt[NIMG];
__device__ uint32_t g_imgdone[NIMG];
__device__ unsigned long long g_cand[(size_t)NIMG*CANDCAP];
__device__ float    g_lx[NIMG*NPTSP];
__device__ float    g_ly[NIMG*NPTSP];
__device__ float    g_q [NIMG*NPTSP];
__device__ int      g_np[NIMG];
__device__ unsigned int g_hdbits[BATCH];
__device__ unsigned int g_done;

// ---------------- threefry2x32 (JAX partitionable semantics) ----------------
__device__ __forceinline__ uint32_t rotl32(uint32_t x, int r) {
    return __funnelshift_l(x, x, r);
}
__device__ __forceinline__ void threefry2x32(uint32_t k0, uint32_t k1,
                                             uint32_t x0, uint32_t x1,
                                             uint32_t& o0, uint32_t& o1) {
    uint32_t ks2 = k0 ^ k1 ^ 0x1BD11BDAu;
    x0 += k0; x1 += k1;
#define TF_RND(r) { x0 += x1; x1 = rotl32(x1, r); x1 ^= x0; }
    TF_RND(13) TF_RND(15) TF_RND(26) TF_RND(6)   x0 += k1;  x1 += ks2 + 1u;
    TF_RND(17) TF_RND(29) TF_RND(16) TF_RND(24)  x0 += ks2; x1 += k0  + 2u;
    TF_RND(13) TF_RND(15) TF_RND(26) TF_RND(6)   x0 += k0;  x1 += k1  + 3u;
    TF_RND(17) TF_RND(29) TF_RND(16) TF_RND(24)  x0 += k1;  x1 += ks2 + 4u;
    TF_RND(13) TF_RND(15) TF_RND(26) TF_RND(6)   x0 += ks2; x1 += k0  + 5u;
#undef TF_RND
    o0 = x0; o1 = x1;
}
// pre-added variant: x1 = k1 + counter already added by caller.
__device__ __forceinline__ uint32_t threefry_xor(uint32_t k0, uint32_t k1,
                                                 uint32_t ks2, uint32_t x1) {
    uint32_t x0 = k0;
#define TF_RND(r) { x0 += x1; x1 = rotl32(x1, r); x1 ^= x0; }
    TF_RND(13) TF_RND(15) TF_RND(26) TF_RND(6)   x0 += k1;  x1 += ks2 + 1u;
    TF_RND(17) TF_RND(29) TF_RND(16) TF_RND(24)  x0 += ks2; x1 += k0  + 2u;
    TF_RND(13) TF_RND(15) TF_RND(26) TF_RND(6)   x0 += k0;  x1 += k1  + 3u;
    TF_RND(17) TF_RND(29) TF_RND(16) TF_RND(24)  x0 += k1;  x1 += ks2 + 4u;
    TF_RND(13) TF_RND(15) TF_RND(26) TF_RND(6)   x0 += ks2; x1 += k0  + 5u;
#undef TF_RND
    return x0 ^ x1;
}
__device__ __forceinline__ float bits_to_uniform(uint32_t bits) {
    return __uint_as_float((bits >> 9) | 0x3F800000u) - 1.0f;
}
// partitionable split(key(1),128): key_b = threefry((0,1), (0,b))
__device__ __forceinline__ void image_key(int b, uint32_t& k0, uint32_t& k1) {
    threefry2x32(0u, 1u, 0u, (uint32_t)b, k0, k1);
}

__device__ __forceinline__ void emit_point(int b, unsigned int pos, uint32_t idx) {
    float x = (float)(idx >> 9), y = (float)(idx & 511);
    g_lx[b * NPTSP + pos] = x;
    g_ly[b * NPTSP + pos] = y;
    g_q [b * NPTSP + pos] = x * x + y * y;
}

// ---------------- selection (runs in the last-finishing block of an image) ---
__device__ __noinline__ void select_image(int b, uint32_t* hist,
                                          unsigned long long* bnd) {
    __shared__ uint32_t tsum[256];
    __shared__ uint32_t esuf[256];
    __shared__ unsigned int s_rc, s_emit, s_bcnt, s_C, s_G;
    int tid = threadIdx.x;
    unsigned int cnt = g_candcnt[b]; if (cnt > CANDCAP) cnt = CANDCAP;
    unsigned int nv  = g_nvalid[b];
    unsigned int needed = (nv < (unsigned)NPTS) ? nv : (unsigned)NPTS;
    bool rescued = false;
    if (cnt < needed) {
        // RESCUE: adaptive tau; statistically never taken.
        if (tid == 0) s_rc = 0u;
        __syncthreads();
        uint32_t k0, k1; image_key(b, k0, k1);
        uint32_t tau = 0u;
        if (nv > 2500u)
            tau = __float_as_uint(2.0f + (1.0f - 2048.0f / (float)nv));
        int lane = tid & 31;
        for (int i = tid; i < NPIX; i += 256) {
            uint32_t vw = g_validbits[b * NWORDS + (i >> 5)];
            bool v = (vw >> lane) & 1u;
            uint32_t o0, o1;
            threefry2x32(k0, k1, 0u, (uint32_t)i, o0, o1);
            uint32_t sb = __float_as_uint(2.0f + bits_to_uniform(o0 ^ o1));
            bool acc = v && (sb >= tau);
            unsigned int amask = __ballot_sync(0xffffffffu, acc);
            if (amask) {
                int leader = __ffs(amask) - 1;
                uint32_t base = 0;
                if (lane == leader) base = atomicAdd(&s_rc, (uint32_t)__popc(amask));
                base = __shfl_sync(0xffffffffu, base, leader);
                if (acc) {
                    uint32_t pos = base + __popc(amask & ((1u << lane) - 1u));
                    if (pos < CANDCAP)
                        g_cand[(size_t)b * CANDCAP + pos] =
                            (((unsigned long long)sb) << 32)
                          | (unsigned long long)(~(uint32_t)i);
                }
            }
        }
        __syncthreads();
        cnt = s_rc; if (cnt > CANDCAP) cnt = CANDCAP;
        rescued = true;
    }
    if (needed > cnt) needed = cnt;

    int npts;
    if (cnt == 0u) {
        npts = 1;
        if (tid == 0) {
            g_lx[b * NPTSP] = 256.0f;
            g_ly[b * NPTSP] = 256.0f;
            g_q [b * NPTSP] = 131072.0f;
        }
    } else if (cnt <= needed) {
        npts = (int)cnt;                      // take everything
        for (unsigned int i = tid; i < cnt; i += 256)
            emit_point(b, i, ~(uint32_t)g_cand[(size_t)b * CANDCAP + i]);
    } else {
        npts = (int)needed;
        const uint32_t SB = rescued ? 0x40000000u : 0x403F0000u;
        const int      SH = rescued ? 12 : 4;
        for (int k = tid; k < 4096; k += 256) hist[k] = 0u;
        if (tid == 0) { s_emit = 0u; s_bcnt = 0u; }
        __syncthreads();
        for (unsigned int i = tid; i < cnt; i += 256) {
            uint32_t sb = (uint32_t)(g_cand[(size_t)b * CANDCAP + i] >> 32);
            int bin = (int)((sb - SB) >> SH); if (bin > 4095) bin = 4095;
            atomicAdd(&hist[bin], 1u);
        }
        __syncthreads();
        {   // suffix scan for cutoff bin C, G = count above C
            uint32_t ls = 0;
            int base = tid * 16;
            for (int k = 0; k < 16; k++) ls += hist[base + k];
            tsum[tid] = ls;
        }
        __syncthreads();
        if (tid < 32) {
            uint32_t g = 0;
            for (int k = 0; k < 8; k++) g += tsum[tid * 8 + k];
            uint32_t sfx = g;
            for (int off = 1; off < 32; off <<= 1) {
                uint32_t o = __shfl_down_sync(0xffffffffu, sfx, off);
                if (tid + off < 32) sfx += o;
            }
            uint32_t cum = sfx - g;
            for (int k = 7; k >= 0; k--) {
                esuf[tid * 8 + k] = cum;
                cum += tsum[tid * 8 + k];
            }
        }
        __syncthreads();
        {
            uint32_t sa = esuf[tid];
            if (sa < needed && sa + tsum[tid] >= needed) {
                uint32_t cum = sa;
                for (int bin = tid * 16 + 15; ; bin--) {
                    uint32_t h = hist[bin];
                    if (cum + h >= needed) { s_C = (unsigned)bin; s_G = cum; break; }
                    cum += h;
                }
            }
        }
        __syncthreads();
        unsigned int C = s_C, G = s_G;
        for (unsigned int i = tid; i < cnt; i += 256) {
            unsigned long long key = g_cand[(size_t)b * CANDCAP + i];
            uint32_t sb = (uint32_t)(key >> 32);
            int bin = (int)((sb - SB) >> SH); if (bin > 4095) bin = 4095;
            if (bin > (int)C) {
                unsigned int pos = atomicAdd(&s_emit, 1u);
                emit_point(b, pos, ~(uint32_t)key);
            } else if (bin == (int)C) {
                unsigned int p = atomicAdd(&s_bcnt, 1u);
                if (p < BNDCAP) bnd[p] = key;
            }
        }
        __syncthreads();
        unsigned int bcnt = s_bcnt; if (bcnt > BNDCAP) bcnt = BNDCAP;
        int n2 = 2; while (n2 < (int)bcnt) n2 <<= 1;
        for (int i = (int)bcnt + tid; i < n2; i += 256) bnd[i] = 0ull;
        __syncthreads();
        for (int k = 2; k <= n2; k <<= 1) {           // sort desc by full key
            for (int j = k >> 1; j > 0; j >>= 1) {
                for (int i = tid; i < n2; i += 256) {
                    int ixj = i ^ j;
                    if (ixj > i) {
                        unsigned long long a = bnd[i], bb = bnd[ixj];
                        if ((a < bb) == ((i & k) == 0)) { bnd[i] = bb; bnd[ixj] = a; }
                    }
                }
                __syncthreads();
            }
        }
        unsigned int take = needed - G; if (take > bcnt) take = bcnt;
        for (unsigned int j = tid; j < take; j += 256)
            emit_point(b, G + j, ~(uint32_t)bnd[j]);
    }
    __syncthreads();
    int pad = (npts + 7) & ~7;                       // sentinels
    for (int j = npts + tid; j < pad; j += 256) {
        g_lx[b * NPTSP + j] = 0.0f;
        g_ly[b * NPTSP + j] = 0.0f;
        g_q [b * NPTSP + j] = 3.0e38f;
    }
    if (tid == 0) {
        g_np[b] = npts;
        g_candcnt[b] = 0u;     // self-clean for graph replay
        g_nvalid[b]  = 0u;
        g_imgdone[b] = 0u;
    }
}

// ---------------- k_fused: Sobel(+sigmoid) + threefry + accept + selection ---
__global__ void __launch_bounds__(256) k_fused(const float* __restrict__ pred,
                                               const float* __restrict__ target) {
    __shared__ __align__(16) unsigned char s_raw[20608];
    float (*s)[514] = reinterpret_cast<float(*)[514]>(s_raw);
    __shared__ unsigned int blkcnt;
    __shared__ uint32_t skey[2];
    __shared__ uint32_t s_tb;
    __shared__ int s_isLast;
    int bx  = blockIdx.x;
    int b   = bx >> 6;
    int r0  = (bx & 63) << 3;
    int tid = threadIdx.x;
    if (tid == 0) {
        blkcnt = 0u;
        // exact bits threshold T: z >= T  <=>  sqrtf(z) > 0.1f (sqrt.rn monotone)
        double mid = (double)0.1f + 3.7252902984619140625e-9;  // c + ulp/2, exact
        double T = mid * mid;                                  // exact (50 bits)
        float t1 = (float)T;
        uint32_t tb = __float_as_uint(t1);
        if ((double)t1 < T) tb++;
        s_tb = tb;
    }
    bool isPred = (b < BATCH);
    const float* src = isPred ? (pred + (size_t)b * NPIX)
                              : (target + (size_t)(b - BATCH) * NPIX);
    for (int idx = tid; idx < 1280; idx += 256) {
        int lr = idx >> 7;
        int c4 = (idx & 127) << 2;
        int gr = r0 + lr - 1;
        float4 v;
        if (gr >= 0 && gr < HDIM) {
            v = *reinterpret_cast<const float4*>(src + ((size_t)gr << 9) + c4);
            if (isPred) {
                v.x = __fdividef(1.0f, 1.0f + __expf(-v.x));
                v.y = __fdividef(1.0f, 1.0f + __expf(-v.y));
                v.z = __fdividef(1.0f, 1.0f + __expf(-v.z));
                v.w = __fdividef(1.0f, 1.0f + __expf(-v.w));
            }
        } else v = make_float4(0.f, 0.f, 0.f, 0.f);
        s[lr][1 + c4] = v.x; s[lr][2 + c4] = v.y;
        s[lr][3 + c4] = v.z; s[lr][4 + c4] = v.w;
        if (c4 == 0) { s[lr][0] = 0.f; s[lr][513] = 0.f; }
    }
    if (tid < 32) {
        uint32_t a, c;
        image_key(b, a, c);
        if (tid == 0) { skey[0] = a; skey[1] = c; }
    }
    __syncthreads();
    const uint32_t k0 = skey[0], k1 = skey[1], tb = s_tb;
    const uint32_t ks2 = k0 ^ k1 ^ 0x1BD11BDAu;
    const int w = tid >> 5, lane = tid & 31;
    const int sc0   = w * 32 + lane + 1;
    const uint32_t ibase = (uint32_t)((r0 << 9) + w * 32 + lane);
    const uint32_t k1i   = k1 + ibase;
    const int vb0   = b * NWORDS + r0 * 16 + w;
    unsigned int myc = 0;
    // half-major iteration with register sliding window: 3 LDS/pixel steady.
#pragma unroll
    for (int h = 0; h < 2; h++) {
        const int sc = sc0 + h * 256;
        const uint32_t k1h = k1i + 256u * (uint32_t)h;
        float AL = s[0][sc-1], AM = s[0][sc], AR = s[0][sc+1];
        float BL = s[1][sc-1], BM = s[1][sc], BR = s[1][sc+1];
#pragma unroll
        for (int row8 = 0; row8 < 8; row8++) {
            float CL = s[row8+2][sc-1], CM = s[row8+2][sc], CR = s[row8+2][sc+1];
            float gx = (AR - AL) + 2.0f * (BR - BL) + (CR - CL);
            float gy = (CL + 2.0f * CM + CR) - (AL + 2.0f * AM + AR);
            float z  = gx * gx + gy * gy + 1e-8f;
            bool v = __float_as_uint(z) >= tb;   // == (sqrtf(z) > 0.1f), exact
            unsigned int word = __ballot_sync(0xffffffffu, v);
            if (lane == 0) {
                g_validbits[vb0 + row8 * 16 + h * 8] = word;
                myc += __popc(word);
            }
            uint32_t rnd = threefry_xor(k0, k1, ks2, k1h + 512u * (uint32_t)row8);
            unsigned int amask = word & __ballot_sync(0xffffffffu, rnd >= KTH9);
            if (amask) {
                bool acc = (amask >> lane) & 1u;
                int leader = __ffs(amask) - 1;
                uint32_t base = 0;
                if (lane == leader)
                    base = atomicAdd(&g_candcnt[b], (uint32_t)__popc(amask));
                base = __shfl_sync(0xffffffffu, base, leader);
                if (acc) {
                    uint32_t pos = base + __popc(amask & ((1u << lane) - 1u));
                    if (pos < CANDCAP) {
                        uint32_t kk = rnd >> 9;
                        float uu = __uint_as_float(kk | 0x3F800000u) - 1.0f;
                        uint32_t sb = __float_as_uint(2.0f + uu);
                        uint32_t i = ibase + 256u * (uint32_t)h + 512u * (uint32_t)row8;
                        g_cand[(size_t)b * CANDCAP + pos] =
                            (((unsigned long long)sb) << 32) | (unsigned long long)(~i);
                    }
                }
            }
            AL = BL; AM = BM; AR = BR;
            BL = CL; BM = CM; BR = CR;
        }
    }
    if (lane == 0 && myc) atomicAdd(&blkcnt, myc);
    __syncthreads();
    if (tid == 0 && blkcnt) atomicAdd(&g_nvalid[b], blkcnt);
    // last-finishing block of this image runs selection
    __threadfence();
    __syncthreads();
    if (tid == 0) {
        unsigned int old = atomicAdd(&g_imgdone[b], 1u);
        s_isLast = (old == 63u);
    }
    __syncthreads();
    if (s_isLast) {
        __threadfence();
        uint32_t* hist = reinterpret_cast<uint32_t*>(s_raw);
        unsigned long long* bnd = reinterpret_cast<unsigned long long*>(s_raw + 16384);
        select_image(b, hist, bnd);
    }
}

// ---------------- k_hd_mean: 512 blocks = 64 img x 2 dir x 4 parts -----------
// FFMA2 packed pair-evals: 1 fma-pipe instr per pair (was 2); FMNMX on alu.
__global__ void __launch_bounds__(128) k_hd_mean(float* __restrict__ out) {
    __shared__ __align__(16) float rx[NPTSP], ry[NPTSP], rq[NPTSP];
    __shared__ float red[4];
    __shared__ int s_last;
    int blk  = blockIdx.x;
    int b    = blk >> 3;
    int dir  = (blk >> 2) & 1;
    int part = blk & 3;
    int tid  = threadIdx.x;
    int qimg = dir ? (BATCH + b) : b;
    int rimg = dir ? b : (BATCH + b);
    int nq  = g_np[qimg];
    int nr8 = (g_np[rimg] + 7) & ~7;
    if (tid == 0) s_last = 0;
    for (int i = tid; i < nr8; i += 128) {
        rx[i] = g_lx[rimg * NPTSP + i];
        ry[i] = g_ly[rimg * NPTSP + i];
        rq[i] = g_q [rimg * NPTSP + i];
    }
    __syncthreads();
    int ch = (nq + PARTS - 1) / PARTS;       // <= 250
    int i0 = part * ch;
    int i1 = (i0 + ch < nq) ? (i0 + ch) : nq;
    int iqA = i0 + tid, iqB = i0 + tid + 128;
    bool actA = iqA < i1, actB = iqB < i1;
    int rdA = actA ? iqA : 0, rdB = actB ? iqB : 0;
    float xA = g_lx[qimg * NPTSP + rdA], yA = g_ly[qimg * NPTSP + rdA];
    float xB = g_lx[qimg * NPTSP + rdB], yB = g_ly[qimg * NPTSP + rdB];
    unsigned long long nxA2 = pack2(-2.0f * xA), nyA2 = pack2(-2.0f * yA);
    unsigned long long nxB2 = pack2(-2.0f * xB), nyB2 = pack2(-2.0f * yB);
    float xxA = fmaf(xA, xA, yA * yA);
    float xxB = fmaf(xB, xB, yB * yB);
    float mA0 = 3.4e38f, mA1 = 3.4e38f, mB0 = 3.4e38f, mB1 = 3.4e38f;
    for (int j = 0; j < nr8; j += 8) {
        // 8 refs = 4 packed f32x2 triples (x, y, q)
        const ulonglong2 tx0 = *reinterpret_cast<const ulonglong2*>(&rx[j]);
        const ulonglong2 ty0 = *reinterpret_cast<const ulonglong2*>(&ry[j]);
        const ulonglong2 tq0 = *reinterpret_cast<const ulonglong2*>(&rq[j]);
        const ulonglong2 tx1 = *reinterpret_cast<const ulonglong2*>(&rx[j + 4]);
        const ulonglong2 ty1 = *reinterpret_cast<const ulonglong2*>(&ry[j + 4]);
        const ulonglong2 tq1 = *reinterpret_cast<const ulonglong2*>(&rq[j + 4]);
        unsigned long long i0v, i1v, i2v, i3v, d0, d1, d2, d3;
        // query A
        FMA2(i0v, ty0.x, nyA2, tq0.x);  FMA2(d0, tx0.x, nxA2, i0v);
        FMA2(i1v, ty0.y, nyA2, tq0.y);  FMA2(d1, tx0.y, nxA2, i1v);
        FMA2(i2v, ty1.x, nyA2, tq1.x);  FMA2(d2, tx1.x, nxA2, i2v);
        FMA2(i3v, ty1.y, nyA2, tq1.y);  FMA2(d3, tx1.y, nxA2, i3v);
        mA0 = fminf(mA0, fminf(lo2(d0), hi2(d0)));
        mA1 = fminf(mA1, fminf(lo2(d1), hi2(d1)));
        mA0 = fminf(mA0, fminf(lo2(d2), hi2(d2)));
        mA1 = fminf(mA1, fminf(lo2(d3), hi2(d3)));
        // query B
        FMA2(i0v, ty0.x, nyB2, tq0.x);  FMA2(d0, tx0.x, nxB2, i0v);
        FMA2(i1v, ty0.y, nyB2, tq0.y);  FMA2(d1, tx0.y, nxB2, i1v);
        FMA2(i2v, ty1.x, nyB2, tq1.x);  FMA2(d2, tx1.x, nxB2, i2v);
        FMA2(i3v, ty1.y, nyB2, tq1.y);  FMA2(d3, tx1.y, nxB2, i3v);
        mB0 = fminf(mB0, fminf(lo2(d0), hi2(d0)));
        mB1 = fminf(mB1, fminf(lo2(d1), hi2(d1)));
        mB0 = fminf(mB0, fminf(lo2(d2), hi2(d2)));
        mB1 = fminf(mB1, fminf(lo2(d3), hi2(d3)));
    }
    float lmax = 0.0f;
    if (actA) lmax = fmaxf(lmax, fmaxf(fminf(mA0, mA1) + xxA, 0.0f));
    if (actB) lmax = fmaxf(lmax, fmaxf(fminf(mB0, mB1) + xxB, 0.0f));
    for (int off = 16; off; off >>= 1)
        lmax = fmaxf(lmax, __shfl_down_sync(0xffffffffu, lmax, off));
    if ((tid & 31) == 0) red[tid >> 5] = lmax;
    __syncthreads();
    if (tid == 0) {
        float vv = fmaxf(fmaxf(red[0], red[1]), fmaxf(red[2], red[3]));
        atomicMax(&g_hdbits[b], __float_as_uint(vv));
        __threadfence();
        unsigned int old = atomicAdd(&g_done, 1u);
        s_last = (old == HDBLOCKS - 1);
    }
    __syncthreads();
    if (s_last && tid == 0) {
        __threadfence();
        float diag = sqrtf((float)(HDIM * HDIM + WDIM * WDIM));
        float ssum = 0.0f;
        for (int i = 0; i < BATCH; i++) {
            float hd = sqrtf(__uint_as_float(g_hdbits[i])) / diag;
            ssum += fminf(fmaxf(hd, 0.0f), 0.1f);
            g_hdbits[i] = 0u;                       // self-clean
        }
        out[0] = ssum / (float)BATCH;
        g_done = 0u;                                // self-clean
    }
}

// ---------------- launch ----------------
extern "C" void kernel_launch(void* const* d_in, const int* in_sizes, int n_in,
                              void* d_out, int out_size) {
    const float* pred   = (const float*)d_in[0];
    const float* target = (const float*)d_in[1];
    float* out = (float*)d_out;

    k_fused<<<NIMG * 64, 256>>>(pred, target);   // Sobel+RNG+accept+selection
    k_hd_mean<<<HDBLOCKS, 128>>>(out);           // Hausdorff + mean
}